// round 9
// baseline (speedup 1.0000x reference)
#include <cuda_runtime.h>
#include <cuda_bf16.h>
#include <math.h>
#include <stdint.h>

// Problem dims
#define BB   4
#define SS   2048
#define DD   512
#define HH   8
#define DKV  64
#define DFF  2048
#define MM   (BB * SS)     // 8192 rows
#define QKVN 1536          // fused Q|K|V output width

// ---------------------------------------------------------------------------
// Scratch (device globals — no allocation allowed)
// ---------------------------------------------------------------------------
__device__ __align__(256) float g_O[MM * DD];       // gemm fp32 out (WO / FFN2)
__device__ __align__(256) float g_Y[MM * DD];       // residual-1 output
__device__ __align__(256) __nv_bfloat16 g_QKVh[MM * QKVN];
__device__ __align__(256) __nv_bfloat16 g_QKVl[MM * QKVN];
__device__ __align__(256) __nv_bfloat16 g_Ahi[MM * DD];   // activation splits [M,512]
__device__ __align__(256) __nv_bfloat16 g_Alo[MM * DD];
__device__ __align__(256) __nv_bfloat16 g_Fhi[MM * DFF];  // FFN hidden splits
__device__ __align__(256) __nv_bfloat16 g_Flo[MM * DFF];
// weights [N,K] row-major, concatenated: qkv rows 0..1535 (K=512), wo, w1, w2
#define WOFF_QKV 0
#define WOFF_O   (QKVN * DD)
#define WOFF_1   (WOFF_O + DD * DD)
#define WOFF_2   (WOFF_1 + DFF * DD)
#define WTOT     (WOFF_2 + DD * DFF)
__device__ __align__(256) __nv_bfloat16 g_Whi[WTOT];
__device__ __align__(256) __nv_bfloat16 g_Wlo[WTOT];
__device__ float g_biasQKV[QKVN];
__device__ float g_maskSA[BB * SS * 2];   // (scale, add) per key
__device__ int g_mflag[1];

// ---------------------------------------------------------------------------
// Helpers
// ---------------------------------------------------------------------------
__device__ __forceinline__ uint32_t smem_u32(const void* p) {
    uint32_t a;
    asm("{ .reg .u64 t; cvta.to.shared.u64 t, %1; cvt.u32.u64 %0, t; }" : "=r"(a) : "l"(p));
    return a;
}
__device__ __forceinline__ void cp16(uint32_t d, const void* g) {
    asm volatile("cp.async.cg.shared.global [%0], [%1], 16;" :: "r"(d), "l"(g));
}
#define CP_COMMIT() asm volatile("cp.async.commit_group;" ::: "memory")
#define CP_WAIT0()  asm volatile("cp.async.wait_group 0;" ::: "memory")
#define CP_WAIT1()  asm volatile("cp.async.wait_group 1;" ::: "memory")

#define LDSM4(r0, r1, r2, r3, a) \
    asm volatile("ldmatrix.sync.aligned.m8n8.x4.shared.b16 {%0,%1,%2,%3}, [%4];" \
                 : "=r"(r0), "=r"(r1), "=r"(r2), "=r"(r3) : "r"(a))
#define LDSM4T(r0, r1, r2, r3, a) \
    asm volatile("ldmatrix.sync.aligned.m8n8.x4.trans.shared.b16 {%0,%1,%2,%3}, [%4];" \
                 : "=r"(r0), "=r"(r1), "=r"(r2), "=r"(r3) : "r"(a))

#define MMA16816(d, a, b) \
    asm volatile("mma.sync.aligned.m16n8k16.row.col.f32.bf16.bf16.f32 " \
                 "{%0,%1,%2,%3},{%4,%5,%6,%7},{%8,%9},{%0,%1,%2,%3};" \
                 : "+f"((d)[0]), "+f"((d)[1]), "+f"((d)[2]), "+f"((d)[3]) \
                 : "r"((a)[0]), "r"((a)[1]), "r"((a)[2]), "r"((a)[3]), \
                   "r"((b)[0]), "r"((b)[1]))

__device__ __forceinline__ uint32_t pack_bf16x2(float a, float b) {
    __nv_bfloat162 v = __floats2bfloat162_rn(a, b);
    return *(uint32_t*)&v;
}

// ---------------------------------------------------------------------------
// Mask canonicalization -> (scale, add) pairs
// ---------------------------------------------------------------------------
__global__ void detect_mask_kernel(const void* __restrict__ m, int* __restrict__ flag)
{
    __shared__ int bad_int, bad_flt;
    if (threadIdx.x == 0) { bad_int = 0; bad_flt = 0; }
    __syncthreads();
    const int* mi = (const int*)m;
    const float* mf = (const float*)m;
    for (int i = threadIdx.x; i < 2048; i += 256) {
        int vi = mi[i];
        if (vi != 0 && vi != 1) bad_int = 1;
        float vf = mf[i];
        if (vf != 0.0f && vf != 1.0f) bad_flt = 1;
    }
    __syncthreads();
    if (threadIdx.x == 0) flag[0] = bad_int ? (bad_flt ? 2 : 1) : 0;
}

__global__ void expand_mask_kernel(const void* __restrict__ m, const int* __restrict__ flag,
                                   float* __restrict__ sa)
{
    int i = blockIdx.x * 256 + threadIdx.x;
    if (i >= BB * SS) return;
    int f = flag[0];
    int v;
    if (f == 0)      v = (((const int*)m)[i]   != 0);
    else if (f == 1) v = (((const float*)m)[i] != 0.0f);
    else             v = (((const unsigned char*)m)[i] != 0);
    sa[i * 2]     = v ? 0.0f   : 0.125f;
    sa[i * 2 + 1] = v ? -1.0e9f : 0.0f;
}

__global__ void concat_bias_kernel(const float* __restrict__ a, const float* __restrict__ b,
                                   const float* __restrict__ c, float* __restrict__ o)
{
    int i = blockIdx.x * 256 + threadIdx.x;
    if (i < 512)          o[i] = a[i];
    else if (i < 1024)    o[i] = b[i - 512];
    else if (i < QKVN)    o[i] = c[i - 1024];
}

// ---------------------------------------------------------------------------
// fp32 -> bf16 hi/lo split
// ---------------------------------------------------------------------------
__global__ __launch_bounds__(256)
void split_bf16_kernel(const float* __restrict__ in, __nv_bfloat16* __restrict__ hi,
                       __nv_bfloat16* __restrict__ lo, int n)
{
    int i = (blockIdx.x * 256 + threadIdx.x) * 4;
    if (i >= n) return;
    float4 v = *(const float4*)(in + i);
    __nv_bfloat16 h0 = __float2bfloat16_rn(v.x);
    __nv_bfloat16 h1 = __float2bfloat16_rn(v.y);
    __nv_bfloat16 h2 = __float2bfloat16_rn(v.z);
    __nv_bfloat16 h3 = __float2bfloat16_rn(v.w);
    __nv_bfloat16 l0 = __float2bfloat16_rn(v.x - __bfloat162float(h0));
    __nv_bfloat16 l1 = __float2bfloat16_rn(v.y - __bfloat162float(h1));
    __nv_bfloat16 l2 = __float2bfloat16_rn(v.z - __bfloat162float(h2));
    __nv_bfloat16 l3 = __float2bfloat16_rn(v.w - __bfloat162float(h3));
    __nv_bfloat162 hv0; hv0.x = h0; hv0.y = h1;
    __nv_bfloat162 hv1; hv1.x = h2; hv1.y = h3;
    __nv_bfloat162 lv0; lv0.x = l0; lv0.y = l1;
    __nv_bfloat162 lv1; lv1.x = l2; lv1.y = l3;
    *(uint2*)(hi + i) = make_uint2(*(uint32_t*)&hv0, *(uint32_t*)&hv1);
    *(uint2*)(lo + i) = make_uint2(*(uint32_t*)&lv0, *(uint32_t*)&lv1);
}

// ---------------------------------------------------------------------------
// mma.sync bf16 split-GEMM (validated R4/R7 @ rel_err ~7e-6)
// ---------------------------------------------------------------------------
#define TPAD 40
#define TILE_B (128 * TPAD * 2)
#define STAGE_B (4 * TILE_B)
#define GSMEM (2 * STAGE_B)

__device__ __forceinline__ void gemm_issue(uint32_t sb, int stage, const __nv_bfloat16* const* srcs,
                                           int K, int kt, int tid)
{
    uint32_t stbase = sb + stage * STAGE_B;
    const int k0 = kt * 32;
#pragma unroll
    for (int t = 0; t < 4; t++) {
        const __nv_bfloat16* s = srcs[t] + k0;
#pragma unroll
        for (int i = 0; i < 2; i++) {
            int idx = tid + i * 256;
            int row = idx >> 2, ch = idx & 3;
            cp16(stbase + t * TILE_B + row * (TPAD * 2) + ch * 16,
                 s + (size_t)row * K + ch * 8);
        }
    }
    CP_COMMIT();
}

__global__ __launch_bounds__(256, 1)
void gemm_mma(const __nv_bfloat16* __restrict__ Ahi, const __nv_bfloat16* __restrict__ Alo,
              const __nv_bfloat16* __restrict__ Whi, const __nv_bfloat16* __restrict__ Wlo,
              const float* __restrict__ bias, float* __restrict__ Cf,
              __nv_bfloat16* __restrict__ Chi, __nv_bfloat16* __restrict__ Clo,
              int M, int N, int K, int relu)
{
    extern __shared__ char sm[];
    const uint32_t sb = smem_u32(sm);
    const int tid = threadIdx.x;
    const int wid = tid >> 5;
    const int lane = tid & 31;
    const int bm = blockIdx.y * 128;
    const int bn = blockIdx.x * 128;
    const int wm = (wid & 1) * 64;
    const int wn = (wid >> 1) * 32;

    const __nv_bfloat16* srcs[4];
    srcs[0] = Ahi + (size_t)bm * K;
    srcs[1] = Alo + (size_t)bm * K;
    srcs[2] = Whi + (size_t)bn * K;
    srcs[3] = Wlo + (size_t)bn * K;

    float acc[4][4][4];
#pragma unroll
    for (int i = 0; i < 4; i++)
#pragma unroll
        for (int j = 0; j < 4; j++)
#pragma unroll
            for (int r = 0; r < 4; r++) acc[i][j][r] = 0.f;

    const int KT = K >> 5;
    gemm_issue(sb, 0, srcs, K, 0, tid);
    gemm_issue(sb, 1, srcs, K, 1, tid);

    const int a_lofs = ((((lane >> 3) & 1) << 3) + (lane & 7)) * (TPAD * 2) + ((lane >> 4) << 4);
    const int b_lofs = ((((lane >> 4) & 1) << 3) + (lane & 7)) * (TPAD * 2) + (((lane >> 3) & 1) << 4);

    for (int kt = 0; kt < KT; kt++) {
        if (kt == KT - 1) { CP_WAIT0(); } else { CP_WAIT1(); }
        __syncthreads();
        const uint32_t base = sb + (kt & 1) * STAGE_B;

#pragma unroll
        for (int ks = 0; ks < 2; ks++) {
            uint32_t ah[4][4], al[4][4], bh[4][2], bl[4][2];
            const uint32_t aoff = base + (wm)*(TPAD * 2) + ks * 32 + a_lofs;
            const uint32_t boff = base + 2 * TILE_B + (wn)*(TPAD * 2) + ks * 32 + b_lofs;
#pragma unroll
            for (int i = 0; i < 4; i++) {
                LDSM4(ah[i][0], ah[i][1], ah[i][2], ah[i][3], aoff + i * 16 * (TPAD * 2));
                LDSM4(al[i][0], al[i][1], al[i][2], al[i][3], aoff + TILE_B + i * 16 * (TPAD * 2));
            }
#pragma unroll
            for (int g = 0; g < 2; g++) {
                LDSM4(bh[2 * g][0], bh[2 * g][1], bh[2 * g + 1][0], bh[2 * g + 1][1],
                      boff + g * 16 * (TPAD * 2));
                LDSM4(bl[2 * g][0], bl[2 * g][1], bl[2 * g + 1][0], bl[2 * g + 1][1],
                      boff + TILE_B + g * 16 * (TPAD * 2));
            }
#pragma unroll
            for (int i = 0; i < 4; i++)
#pragma unroll
                for (int j = 0; j < 4; j++) MMA16816(acc[i][j], ah[i], bh[j]);
#pragma unroll
            for (int i = 0; i < 4; i++)
#pragma unroll
                for (int j = 0; j < 4; j++) MMA16816(acc[i][j], al[i], bh[j]);
#pragma unroll
            for (int i = 0; i < 4; i++)
#pragma unroll
                for (int j = 0; j < 4; j++) MMA16816(acc[i][j], ah[i], bl[j]);
        }
        __syncthreads();
        if (kt + 2 < KT) gemm_issue(sb, kt & 1, srcs, K, kt + 2, tid);
    }

    const int rr = lane >> 2;
    const int cc = (lane & 3) * 2;
#pragma unroll
    for (int i = 0; i < 4; i++) {
#pragma unroll
        for (int j = 0; j < 4; j++) {
            int r0 = bm + wm + i * 16 + rr;
            int c = bn + wn + j * 8 + cc;
            float b0 = __ldg(bias + c), b1 = __ldg(bias + c + 1);
            float v00 = acc[i][j][0] + b0, v01 = acc[i][j][1] + b1;
            float v10 = acc[i][j][2] + b0, v11 = acc[i][j][3] + b1;
            if (relu) {
                v00 = fmaxf(v00, 0.f); v01 = fmaxf(v01, 0.f);
                v10 = fmaxf(v10, 0.f); v11 = fmaxf(v11, 0.f);
            }
            size_t o0 = (size_t)r0 * N + c;
            size_t o1 = (size_t)(r0 + 8) * N + c;
            if (Cf) {
                *(float2*)(Cf + o0) = make_float2(v00, v01);
                *(float2*)(Cf + o1) = make_float2(v10, v11);
            }
            if (Chi) {
                __nv_bfloat162 h0 = __floats2bfloat162_rn(v00, v01);
                __nv_bfloat162 h1 = __floats2bfloat162_rn(v10, v11);
                __nv_bfloat162 l0 = __floats2bfloat162_rn(v00 - __bfloat162float(h0.x),
                                                          v01 - __bfloat162float(h0.y));
                __nv_bfloat162 l1 = __floats2bfloat162_rn(v10 - __bfloat162float(h1.x),
                                                          v11 - __bfloat162float(h1.y));
                *(__nv_bfloat162*)(Chi + o0) = h0;
                *(__nv_bfloat162*)(Chi + o1) = h1;
                *(__nv_bfloat162*)(Clo + o0) = l0;
                *(__nv_bfloat162*)(Clo + o1) = l1;
            }
        }
    }
}

// ---------------------------------------------------------------------------
// mma.sync flash attention, 128-q tile + double-buffered K/V.
// Block = (b, h, 128-q-tile), 256 thr / 8 warps; warp w owns q rows w*16..+16.
// smem: Qh 0 (18432), Ql 18432 (18432); stage s at 36864 + s*37376:
//   Kh +0, Kl +9216, Vh +18432, Vl +27648, maskSA +36864 (512B)
// ---------------------------------------------------------------------------
#define APITCHB 144
#define ATT_QB   18432
#define ATT_STG  37376
#define ATT_STG0 (2 * ATT_QB)
#define ATT_SMEM (ATT_STG0 + 2 * ATT_STG)    // 111616
#define ATT_NIT  (SS / 64)                   // 32

__device__ __forceinline__ void att_issue_kv(uint32_t stbase,
        const __nv_bfloat16* __restrict__ QKVh, const __nv_bfloat16* __restrict__ QKVl,
        const float* __restrict__ maskSA, int b, int j0, int tid)
{
    const size_t kb = ((size_t)b * SS + j0) * QKVN + 512;
#pragma unroll
    for (int i = 0; i < 8; i++) {
        int idx = tid + i * 256;             // 0..2047
        int t = idx >> 9;                    // 0 Kh, 1 Kl, 2 Vh, 3 Vl
        int row = (idx >> 3) & 63;
        int ch = idx & 7;
        const __nv_bfloat16* base = (t == 0 || t == 2) ? QKVh : QKVl;
        size_t goff = kb + (size_t)row * QKVN + ((t >= 2) ? 512 : 0) + ch * 8;
        cp16(stbase + t * 9216 + row * APITCHB + ch * 16, base + goff);
    }
    if (tid < 32) cp16(stbase + 36864 + tid * 16, maskSA + ((size_t)b * SS + j0) * 2 + tid * 4);
    CP_COMMIT();
}

__global__ __launch_bounds__(256, 1)
void attention_mma(const __nv_bfloat16* __restrict__ QKVh, const __nv_bfloat16* __restrict__ QKVl,
                   const float* __restrict__ maskSA,
                   __nv_bfloat16* __restrict__ Ohi, __nv_bfloat16* __restrict__ Olo)
{
    extern __shared__ char ab[];
    const uint32_t sb = smem_u32(ab);
    const int b = blockIdx.z, h = blockIdx.y, q0 = blockIdx.x * 128;
    const int tid = threadIdx.x, wid = tid >> 5, lane = tid & 31;

    // --- load Q hi/lo tiles (128 rows, once) ---
    {
        const size_t rb = ((size_t)b * SS + q0) * QKVN + h * DKV;
#pragma unroll
        for (int i = 0; i < 8; i++) {
            int idx = tid + i * 256;             // 0..2047
            int t = idx >> 10;                   // 0 hi, 1 lo
            int row = (idx >> 3) & 127;
            int ch = idx & 7;
            const __nv_bfloat16* src = (t ? QKVl : QKVh) + rb + (size_t)row * QKVN + ch * 8;
            cp16(sb + t * ATT_QB + row * APITCHB + ch * 16, src);
        }
    }
    CP_COMMIT();

    // prefetch first two K/V stages
    att_issue_kv(sb + ATT_STG0,           QKVh + h * DKV, QKVl + h * DKV, maskSA, b, 0, tid);
    att_issue_kv(sb + ATT_STG0 + ATT_STG, QKVh + h * DKV, QKVl + h * DKV, maskSA, b, 64, tid);

    // per-lane row state: rows (wid*16 + lane>>2) and +8
    float m0 = -1e30f, m1 = -1e30f, l0 = 0.f, l1 = 0.f;
    float o[8][4];
#pragma unroll
    for (int j = 0; j < 8; j++)
#pragma unroll
        for (int r = 0; r < 4; r++) o[j][r] = 0.f;

    // ldmatrix lane offsets
    const uint32_t a_lofs = (uint32_t)((wid * 16 + (((lane >> 3) & 1) << 3) + (lane & 7)) * APITCHB
                                       + ((lane >> 4) << 4));
    const uint32_t b_lofs = (uint32_t)(((((lane >> 4) & 1) << 3) + (lane & 7)) * APITCHB
                                       + (((lane >> 3) & 1) << 4));
    const uint32_t v_lofs = (uint32_t)((lane & 15) * APITCHB + ((lane >> 4) << 4));

    for (int it = 0; it < ATT_NIT; it++) {
        const uint32_t so = ATT_STG0 + (uint32_t)(it & 1) * ATT_STG;
        const uint32_t sKh = sb + so, sKl = sb + so + 9216;
        const uint32_t sVh = sb + so + 18432, sVl = sb + so + 27648;

        if (it < ATT_NIT - 1) { CP_WAIT1(); } else { CP_WAIT0(); }
        __syncthreads();

        // --- S = Q K^T (3-pass split) ---
        float s[8][4];
#pragma unroll
        for (int j = 0; j < 8; j++)
#pragma unroll
            for (int r = 0; r < 4; r++) s[j][r] = 0.f;

#pragma unroll
        for (int kc = 0; kc < 4; kc++) {
            uint32_t qh[4], ql[4];
            LDSM4(qh[0], qh[1], qh[2], qh[3], sb + a_lofs + kc * 32);
            LDSM4(ql[0], ql[1], ql[2], ql[3], sb + ATT_QB + a_lofs + kc * 32);
#pragma unroll
            for (int g = 0; g < 4; g++) {
                uint32_t kh0[2], kh1[2], kl0[2], kl1[2];
                LDSM4(kh0[0], kh0[1], kh1[0], kh1[1], sKh + b_lofs + g * 16 * APITCHB + kc * 32);
                LDSM4(kl0[0], kl0[1], kl1[0], kl1[1], sKl + b_lofs + g * 16 * APITCHB + kc * 32);
                MMA16816(s[2 * g],     qh, kh0);
                MMA16816(s[2 * g],     ql, kh0);
                MMA16816(s[2 * g],     qh, kl0);
                MMA16816(s[2 * g + 1], qh, kh1);
                MMA16816(s[2 * g + 1], ql, kh1);
                MMA16816(s[2 * g + 1], qh, kl1);
            }
        }

        // --- scale + mask: s' = s*scale + add ---
        {
            const char* mskp = ab + so + 36864;
#pragma unroll
            for (int j = 0; j < 8; j++) {
                float4 f = *(const float4*)(mskp + (j * 8 + (lane & 3) * 2) * 8);
                s[j][0] = fmaf(s[j][0], f.x, f.y);
                s[j][1] = fmaf(s[j][1], f.z, f.w);
                s[j][2] = fmaf(s[j][2], f.x, f.y);
                s[j][3] = fmaf(s[j][3], f.z, f.w);
            }
        }

        // --- online softmax ---
        float mx0 = -1e30f, mx1 = -1e30f;
#pragma unroll
        for (int j = 0; j < 8; j++) {
            mx0 = fmaxf(mx0, fmaxf(s[j][0], s[j][1]));
            mx1 = fmaxf(mx1, fmaxf(s[j][2], s[j][3]));
        }
        mx0 = fmaxf(mx0, __shfl_xor_sync(0xffffffffu, mx0, 1));
        mx0 = fmaxf(mx0, __shfl_xor_sync(0xffffffffu, mx0, 2));
        mx1 = fmaxf(mx1, __shfl_xor_sync(0xffffffffu, mx1, 1));
        mx1 = fmaxf(mx1, __shfl_xor_sync(0xffffffffu, mx1, 2));

        float mn0 = fmaxf(m0, mx0), mn1 = fmaxf(m1, mx1);
        float al0 = __expf(m0 - mn0), al1 = __expf(m1 - mn1);
        float sum0 = 0.f, sum1 = 0.f;
#pragma unroll
        for (int j = 0; j < 8; j++) {
            s[j][0] = __expf(s[j][0] - mn0); sum0 += s[j][0];
            s[j][1] = __expf(s[j][1] - mn0); sum0 += s[j][1];
            s[j][2] = __expf(s[j][2] - mn1); sum1 += s[j][2];
            s[j][3] = __expf(s[j][3] - mn1); sum1 += s[j][3];
        }
        sum0 += __shfl_xor_sync(0xffffffffu, sum0, 1);
        sum0 += __shfl_xor_sync(0xffffffffu, sum0, 2);
        sum1 += __shfl_xor_sync(0xffffffffu, sum1, 1);
        sum1 += __shfl_xor_sync(0xffffffffu, sum1, 2);
        l0 = l0 * al0 + sum0; m0 = mn0;
        l1 = l1 * al1 + sum1; m1 = mn1;
#pragma unroll
        for (int j = 0; j < 8; j++) {
            o[j][0] *= al0; o[j][1] *= al0;
            o[j][2] *= al1; o[j][3] *= al1;
        }

        // --- O += P V (3-pass split; P from accumulators) ---
#pragma unroll
        for (int kc = 0; kc < 4; kc++) {
            uint32_t ph[4], pl[4];
            {
                int j = 2 * kc;
                float h00 = s[j][0],   h01 = s[j][1],   h10 = s[j][2],   h11 = s[j][3];
                float g00 = s[j+1][0], g01 = s[j+1][1], g10 = s[j+1][2], g11 = s[j+1][3];
                ph[0] = pack_bf16x2(h00, h01);
                ph[1] = pack_bf16x2(h10, h11);
                ph[2] = pack_bf16x2(g00, g01);
                ph[3] = pack_bf16x2(g10, g11);
                __nv_bfloat162 t0 = *(__nv_bfloat162*)&ph[0];
                __nv_bfloat162 t1 = *(__nv_bfloat162*)&ph[1];
                __nv_bfloat162 t2 = *(__nv_bfloat162*)&ph[2];
                __nv_bfloat162 t3 = *(__nv_bfloat162*)&ph[3];
                pl[0] = pack_bf16x2(h00 - __bfloat162float(t0.x), h01 - __bfloat162float(t0.y));
                pl[1] = pack_bf16x2(h10 - __bfloat162float(t1.x), h11 - __bfloat162float(t1.y));
                pl[2] = pack_bf16x2(g00 - __bfloat162float(t2.x), g01 - __bfloat162float(t2.y));
                pl[3] = pack_bf16x2(g10 - __bfloat162float(t3.x), g11 - __bfloat162float(t3.y));
            }
#pragma unroll
            for (int p = 0; p < 4; p++) {
                uint32_t vh0[2], vh1[2], vl0[2], vl1[2];
                LDSM4T(vh0[0], vh0[1], vh1[0], vh1[1],
                       sVh + v_lofs + kc * 16 * APITCHB + p * 32);
                LDSM4T(vl0[0], vl0[1], vl1[0], vl1[1],
                       sVl + v_lofs + kc * 16 * APITCHB + p * 32);
                MMA16816(o[2 * p],     ph, vh0);
                MMA16816(o[2 * p],     pl, vh0);
                MMA16816(o[2 * p],     ph, vl0);
                MMA16816(o[2 * p + 1], ph, vh1);
                MMA16816(o[2 * p + 1], pl, vh1);
                MMA16816(o[2 * p + 1], ph, vl1);
            }
        }
        __syncthreads();   // all reads of this stage done
        if (it + 2 < ATT_NIT)
            att_issue_kv(sb + so, QKVh + h * DKV, QKVl + h * DKV, maskSA, b, (it + 2) * 64, tid);
    }

    // --- epilogue: write bf16 hi/lo of O (batch offset included) ---
    const float inv0 = 1.0f / l0, inv1 = 1.0f / l1;
    const size_t rg = (size_t)b * SS + q0 + wid * 16 + (lane >> 2);
    const int cb = h * DKV + (lane & 3) * 2;
#pragma unroll
    for (int j = 0; j < 8; j++) {
        size_t off0 = rg * DD + cb + j * 8;
        size_t off1 = (rg + 8) * DD + cb + j * 8;
        float v00 = o[j][0] * inv0, v01 = o[j][1] * inv0;
        float v10 = o[j][2] * inv1, v11 = o[j][3] * inv1;
        uint32_t h0 = pack_bf16x2(v00, v01);
        uint32_t h1 = pack_bf16x2(v10, v11);
        __nv_bfloat162 t0 = *(__nv_bfloat162*)&h0;
        __nv_bfloat162 t1 = *(__nv_bfloat162*)&h1;
        uint32_t z0 = pack_bf16x2(v00 - __bfloat162float(t0.x), v01 - __bfloat162float(t0.y));
        uint32_t z1 = pack_bf16x2(v10 - __bfloat162float(t1.x), v11 - __bfloat162float(t1.y));
        *(uint32_t*)(Ohi + off0) = h0;
        *(uint32_t*)(Ohi + off1) = h1;
        *(uint32_t*)(Olo + off0) = z0;
        *(uint32_t*)(Olo + off1) = z1;
    }
}

// ---------------------------------------------------------------------------
// Residual + LayerNorm (unbiased var, scalar gamma/beta), optional bf16 split
// ---------------------------------------------------------------------------
__global__ __launch_bounds__(128)
void ln_add_kernel(const float* __restrict__ X, const float* __restrict__ Z,
                   const float* __restrict__ g, const float* __restrict__ beta,
                   float* __restrict__ Out,
                   __nv_bfloat16* __restrict__ Ohi, __nv_bfloat16* __restrict__ Olo)
{
    __shared__ float red[4];
    const int row = blockIdx.x;
    const int t = threadIdx.x;
    const float4 zv = ((const float4*)(Z + (size_t)row * DD))[t];

    float s = zv.x + zv.y + zv.z + zv.w;
#pragma unroll
    for (int off = 16; off > 0; off >>= 1) s += __shfl_down_sync(0xffffffffu, s, off);
    if ((t & 31) == 0) red[t >> 5] = s;
    __syncthreads();
    float mean = (red[0] + red[1] + red[2] + red[3]) * (1.0f / DD);
    __syncthreads();

    float d0 = zv.x - mean, d1 = zv.y - mean, d2 = zv.z - mean, d3 = zv.w - mean;
    float ss = d0 * d0 + d1 * d1 + d2 * d2 + d3 * d3;
#pragma unroll
    for (int off = 16; off > 0; off >>= 1) ss += __shfl_down_sync(0xffffffffu, ss, off);
    if ((t & 31) == 0) red[t >> 5] = ss;
    __syncthreads();
    float var = (red[0] + red[1] + red[2] + red[3]) * (1.0f / (DD - 1));

    float inv = rsqrtf(var + 1e-6f);
    float gg = *g, bb = *beta;

    const float4 xv = ((const float4*)(X + (size_t)row * DD))[t];
    float4 o;
    o.x = xv.x + gg * d0 * inv + bb;
    o.y = xv.y + gg * d1 * inv + bb;
    o.z = xv.z + gg * d2 * inv + bb;
    o.w = xv.w + gg * d3 * inv + bb;
    ((float4*)(Out + (size_t)row * DD))[t] = o;

    if (Ohi) {
        size_t off = (size_t)row * DD + t * 4;
        __nv_bfloat162 h0 = __floats2bfloat162_rn(o.x, o.y);
        __nv_bfloat162 h1 = __floats2bfloat162_rn(o.z, o.w);
        __nv_bfloat162 l0 = __floats2bfloat162_rn(o.x - __bfloat162float(h0.x),
                                                  o.y - __bfloat162float(h0.y));
        __nv_bfloat162 l1 = __floats2bfloat162_rn(o.z - __bfloat162float(h1.x),
                                                  o.w - __bfloat162float(h1.y));
        *(__nv_bfloat162*)(Ohi + off)     = h0;
        *(__nv_bfloat162*)(Ohi + off + 2) = h1;
        *(__nv_bfloat162*)(Olo + off)     = l0;
        *(__nv_bfloat162*)(Olo + off + 2) = l1;
    }
}

// ---------------------------------------------------------------------------
// Launch
// ---------------------------------------------------------------------------
extern "C" void kernel_launch(void* const* d_in, const int* in_sizes, int n_in,
                              void* d_out, int out_size)
{
    const float* x    = (const float*)d_in[0];
    const void*  mraw = (const void*)d_in[1];
    const float* wq   = (const float*)d_in[2];
    const float* bq   = (const float*)d_in[3];
    const float* wk   = (const float*)d_in[4];
    const float* bk   = (const float*)d_in[5];
    const float* wv   = (const float*)d_in[6];
    const float* bv   = (const float*)d_in[7];
    const float* wo   = (const float*)d_in[8];
    const float* bo   = (const float*)d_in[9];
    const float* w1   = (const float*)d_in[10];
    const float* b1   = (const float*)d_in[11];
    const float* w2   = (const float*)d_in[12];
    const float* b2   = (const float*)d_in[13];
    const float* g1   = (const float*)d_in[14];
    const float* be1  = (const float*)d_in[15];
    const float* g2   = (const float*)d_in[16];
    const float* be2  = (const float*)d_in[17];
    float* out = (float*)d_out;

    float *pO, *pY, *pBias, *pMSA;
    __nv_bfloat16 *pQKVh, *pQKVl, *pAhi, *pAlo, *pFhi, *pFlo, *pWhi, *pWlo;
    int* pMF;
    cudaGetSymbolAddress((void**)&pO, g_O);
    cudaGetSymbolAddress((void**)&pY, g_Y);
    cudaGetSymbolAddress((void**)&pQKVh, g_QKVh);
    cudaGetSymbolAddress((void**)&pQKVl, g_QKVl);
    cudaGetSymbolAddress((void**)&pAhi, g_Ahi);
    cudaGetSymbolAddress((void**)&pAlo, g_Alo);
    cudaGetSymbolAddress((void**)&pFhi, g_Fhi);
    cudaGetSymbolAddress((void**)&pFlo, g_Flo);
    cudaGetSymbolAddress((void**)&pWhi, g_Whi);
    cudaGetSymbolAddress((void**)&pWlo, g_Wlo);
    cudaGetSymbolAddress((void**)&pBias, g_biasQKV);
    cudaGetSymbolAddress((void**)&pMSA, g_maskSA);
    cudaGetSymbolAddress((void**)&pMF, g_mflag);

    cudaFuncSetAttribute(gemm_mma, cudaFuncAttributeMaxDynamicSharedMemorySize, GSMEM);
    cudaFuncSetAttribute(attention_mma, cudaFuncAttributeMaxDynamicSharedMemorySize, ATT_SMEM);

    // mask + bias prep
    detect_mask_kernel<<<1, 256>>>(mraw, pMF);
    expand_mask_kernel<<<(BB * SS + 255) / 256, 256>>>(mraw, pMF, pMSA);
    concat_bias_kernel<<<(QKVN + 255) / 256, 256>>>(bq, bk, bv, pBias);

    // weight splits
    split_bf16_kernel<<<(DD * DD) / 1024, 256>>>(wq, pWhi + WOFF_QKV,            pWlo + WOFF_QKV,            DD * DD);
    split_bf16_kernel<<<(DD * DD) / 1024, 256>>>(wk, pWhi + WOFF_QKV + DD * DD,  pWlo + WOFF_QKV + DD * DD,  DD * DD);
    split_bf16_kernel<<<(DD * DD) / 1024, 256>>>(wv, pWhi + WOFF_QKV + 2*DD*DD,  pWlo + WOFF_QKV + 2*DD*DD,  DD * DD);
    split_bf16_kernel<<<(DD * DD) / 1024, 256>>>(wo, pWhi + WOFF_O,  pWlo + WOFF_O,  DD * DD);
    split_bf16_kernel<<<(DFF * DD) / 1024, 256>>>(w1, pWhi + WOFF_1, pWlo + WOFF_1, DFF * DD);
    split_bf16_kernel<<<(DD * DFF) / 1024, 256>>>(w2, pWhi + WOFF_2, pWlo + WOFF_2, DD * DFF);

    // x split
    split_bf16_kernel<<<(MM * DD) / 1024, 256>>>(x, pAhi, pAlo, MM * DD);

    // fused QKV projection -> bf16 hi/lo only
    dim3 gQKV(QKVN / 128, MM / 128);
    gemm_mma<<<gQKV, 256, GSMEM>>>(pAhi, pAlo, pWhi + WOFF_QKV, pWlo + WOFF_QKV,
                                   pBias, ((float*)0), pQKVh, pQKVl,
                                   MM, QKVN, DD, 0);

    // attention (tensor-core, 128-q tiles, double-buffered K/V)
    dim3 gAtt(SS / 128, HH, BB);
    attention_mma<<<gAtt, 256, ATT_SMEM>>>(pQKVh, pQKVl, pMSA, pAhi, pAlo);

    // WO projection -> fp32 pO
    dim3 gProj(DD / 128, MM / 128);
    gemm_mma<<<gProj, 256, GSMEM>>>(pAhi, pAlo, pWhi + WOFF_O, pWlo + WOFF_O,
                                    bo, pO, ((__nv_bfloat16*)0), ((__nv_bfloat16*)0),
                                    MM, DD, DD, 0);

    // residual 1 + LN -> Y (fp32) + split into pAhi/pAlo
    ln_add_kernel<<<MM, 128>>>(x, pO, g1, be1, pY, pAhi, pAlo);

    // FFN1: relu, bf16 split out only
    dim3 gFF1(DFF / 128, MM / 128);
    gemm_mma<<<gFF1, 256, GSMEM>>>(pAhi, pAlo, pWhi + WOFF_1, pWlo + WOFF_1,
                                   b1, ((float*)0), pFhi, pFlo,
                                   MM, DFF, DD, 1);

    // FFN2 -> fp32 pO
    gemm_mma<<<gProj, 256, GSMEM>>>(pFhi, pFlo, pWhi + WOFF_2, pWlo + WOFF_2,
                                    b2, pO, ((__nv_bfloat16*)0), ((__nv_bfloat16*)0),
                                    MM, DD, DFF, 0);

    // residual 2 + LN -> out
    ln_add_kernel<<<MM, 128>>>(pY, pO, g2, be2, out, ((__nv_bfloat16*)0), ((__nv_bfloat16*)0));
}

// round 12
// speedup vs baseline: 1.2047x; 1.2047x over previous
#include <cuda_runtime.h>
#include <cuda_bf16.h>
#include <math.h>
#include <stdint.h>

// Problem dims
#define BB   4
#define SS   2048
#define DD   512
#define HH   8
#define DKV  64
#define DFF  2048
#define MM   (BB * SS)     // 8192 rows
#define QKVN 1536          // fused Q|K|V output width

// ---------------------------------------------------------------------------
// Scratch (device globals — no allocation allowed)
// ---------------------------------------------------------------------------
__device__ __align__(256) float g_O[MM * DD];       // gemm fp32 out (WO / FFN2)
__device__ __align__(256) float g_Y[MM * DD];       // residual-1 output
__device__ __align__(256) __nv_bfloat16 g_QKVh[MM * QKVN];
__device__ __align__(256) __nv_bfloat16 g_QKVl[MM * QKVN];
__device__ __align__(256) __nv_bfloat16 g_Ahi[MM * DD];   // activation splits [M,512]
__device__ __align__(256) __nv_bfloat16 g_Alo[MM * DD];
__device__ __align__(256) __nv_bfloat16 g_Fhi[MM * DFF];  // FFN hidden splits
__device__ __align__(256) __nv_bfloat16 g_Flo[MM * DFF];
// weights [N,K] row-major, concatenated: qkv rows 0..1535 (K=512), wo, w1, w2
#define WOFF_QKV 0
#define WOFF_O   (QKVN * DD)
#define WOFF_1   (WOFF_O + DD * DD)
#define WOFF_2   (WOFF_1 + DFF * DD)
#define WTOT     (WOFF_2 + DD * DFF)
__device__ __align__(256) __nv_bfloat16 g_Whi[WTOT];
__device__ __align__(256) __nv_bfloat16 g_Wlo[WTOT];
__device__ float g_biasQKV[QKVN];
__device__ float g_maskSA[BB * SS * 2];   // compacted (scale, add) per key slot
__device__ int   g_cidx[BB * SS];         // compacted key indices per batch
__device__ int   g_nb[BB];                // unmasked key count per batch
__device__ int   g_mflag[1];

// ---------------------------------------------------------------------------
// Helpers
// ---------------------------------------------------------------------------
__device__ __forceinline__ uint32_t smem_u32(const void* p) {
    uint32_t a;
    asm("{ .reg .u64 t; cvta.to.shared.u64 t, %1; cvt.u32.u64 %0, t; }" : "=r"(a) : "l"(p));
    return a;
}
__device__ __forceinline__ void cp16(uint32_t d, const void* g) {
    asm volatile("cp.async.cg.shared.global [%0], [%1], 16;" :: "r"(d), "l"(g));
}
#define CP_COMMIT() asm volatile("cp.async.commit_group;" ::: "memory")
#define CP_WAIT0()  asm volatile("cp.async.wait_group 0;" ::: "memory")
#define CP_WAIT1()  asm volatile("cp.async.wait_group 1;" ::: "memory")

#define LDSM4(r0, r1, r2, r3, a) \
    asm volatile("ldmatrix.sync.aligned.m8n8.x4.shared.b16 {%0,%1,%2,%3}, [%4];" \
                 : "=r"(r0), "=r"(r1), "=r"(r2), "=r"(r3) : "r"(a))
#define LDSM4T(r0, r1, r2, r3, a) \
    asm volatile("ldmatrix.sync.aligned.m8n8.x4.trans.shared.b16 {%0,%1,%2,%3}, [%4];" \
                 : "=r"(r0), "=r"(r1), "=r"(r2), "=r"(r3) : "r"(a))

#define MMA16816(d, a, b) \
    asm volatile("mma.sync.aligned.m16n8k16.row.col.f32.bf16.bf16.f32 " \
                 "{%0,%1,%2,%3},{%4,%5,%6,%7},{%8,%9},{%0,%1,%2,%3};" \
                 : "+f"((d)[0]), "+f"((d)[1]), "+f"((d)[2]), "+f"((d)[3]) \
                 : "r"((a)[0]), "r"((a)[1]), "r"((a)[2]), "r"((a)[3]), \
                   "r"((b)[0]), "r"((b)[1]))

__device__ __forceinline__ uint32_t pack_bf16x2(float a, float b) {
    __nv_bfloat162 v = __floats2bfloat162_rn(a, b);
    return *(uint32_t*)&v;
}

// ---------------------------------------------------------------------------
// Mask canonicalization
// ---------------------------------------------------------------------------
__global__ void detect_mask_kernel(const void* __restrict__ m, int* __restrict__ flag)
{
    __shared__ int bad_int, bad_flt;
    if (threadIdx.x == 0) { bad_int = 0; bad_flt = 0; }
    __syncthreads();
    const int* mi = (const int*)m;
    const float* mf = (const float*)m;
    for (int i = threadIdx.x; i < 2048; i += 256) {
        int vi = mi[i];
        if (vi != 0 && vi != 1) bad_int = 1;
        float vf = mf[i];
        if (vf != 0.0f && vf != 1.0f) bad_flt = 1;
    }
    __syncthreads();
    if (threadIdx.x == 0) flag[0] = bad_int ? (bad_flt ? 2 : 1) : 0;
}

// Compact unmasked keys per batch (stable order). One block per batch, 512 thr.
// Outputs: cidx (compacted indices, tail clamped to first valid), msa (scale,add)
// per compacted slot, nb (count). All-masked fallback: identity + (0,0) = uniform.
__global__ __launch_bounds__(512)
void compact_mask_kernel(const void* __restrict__ m, const int* __restrict__ flag,
                         int* __restrict__ cidx, float* __restrict__ msa,
                         int* __restrict__ nb)
{
    __shared__ int wsum[16];
    __shared__ int first_s;
    const int b = blockIdx.x;
    const int t = threadIdx.x;
    const int f = flag[0];

    int keep[4];
#pragma unroll
    for (int k = 0; k < 4; k++) {
        int gi = b * SS + t * 4 + k;
        int v;
        if (f == 0)      v = (((const int*)m)[gi] != 0);
        else if (f == 1) v = (((const float*)m)[gi] != 0.0f);
        else             v = (((const unsigned char*)m)[gi] != 0);
        keep[k] = !v;
    }
    int cnt = keep[0] + keep[1] + keep[2] + keep[3];

    int incl = cnt;
#pragma unroll
    for (int off = 1; off < 32; off <<= 1) {
        int nv = __shfl_up_sync(0xffffffffu, incl, off);
        if ((t & 31) >= off) incl += nv;
    }
    if ((t & 31) == 31) wsum[t >> 5] = incl;
    __syncthreads();
    if (t < 16) {
        int v = wsum[t];
#pragma unroll
        for (int off = 1; off < 16; off <<= 1) {
            int nv = __shfl_up_sync(0x0000ffffu, v, off);
            if (t >= off) v += nv;
        }
        wsum[t] = v;
    }
    __syncthreads();
    const int total = wsum[15];
    int pos = ((t >> 5) ? wsum[(t >> 5) - 1] : 0) + incl - cnt;
#pragma unroll
    for (int k = 0; k < 4; k++) {
        if (keep[k]) {
            cidx[b * SS + pos] = t * 4 + k;
            if (pos == 0) first_s = t * 4 + k;
            pos++;
        }
    }
    __syncthreads();
    const int fi = (total > 0) ? first_s : 0;
    for (int p = t; p < SS; p += 512) {
        if (total > 0) {
            if (p >= total) cidx[b * SS + p] = fi;
            msa[(b * SS + p) * 2]     = (p < total) ? 0.125f : 0.0f;
            msa[(b * SS + p) * 2 + 1] = (p < total) ? 0.0f : -1.0e9f;
        } else {
            cidx[b * SS + p] = p;
            msa[(b * SS + p) * 2]     = 0.0f;
            msa[(b * SS + p) * 2 + 1] = 0.0f;
        }
    }
    if (t == 0) nb[b] = (total > 0) ? total : SS;
}

__global__ void concat_bias_kernel(const float* __restrict__ a, const float* __restrict__ b,
                                   const float* __restrict__ c, float* __restrict__ o)
{
    int i = blockIdx.x * 256 + threadIdx.x;
    if (i < 512)          o[i] = a[i];
    else if (i < 1024)    o[i] = b[i - 512];
    else if (i < QKVN)    o[i] = c[i - 1024];
}

// ---------------------------------------------------------------------------
// fp32 -> bf16 hi/lo split
// ---------------------------------------------------------------------------
__global__ __launch_bounds__(256)
void split_bf16_kernel(const float* __restrict__ in, __nv_bfloat16* __restrict__ hi,
                       __nv_bfloat16* __restrict__ lo, int n)
{
    int i = (blockIdx.x * 256 + threadIdx.x) * 4;
    if (i >= n) return;
    float4 v = *(const float4*)(in + i);
    __nv_bfloat16 h0 = __float2bfloat16_rn(v.x);
    __nv_bfloat16 h1 = __float2bfloat16_rn(v.y);
    __nv_bfloat16 h2 = __float2bfloat16_rn(v.z);
    __nv_bfloat16 h3 = __float2bfloat16_rn(v.w);
    __nv_bfloat16 l0 = __float2bfloat16_rn(v.x - __bfloat162float(h0));
    __nv_bfloat16 l1 = __float2bfloat16_rn(v.y - __bfloat162float(h1));
    __nv_bfloat16 l2 = __float2bfloat16_rn(v.z - __bfloat162float(h2));
    __nv_bfloat16 l3 = __float2bfloat16_rn(v.w - __bfloat162float(h3));
    __nv_bfloat162 hv0; hv0.x = h0; hv0.y = h1;
    __nv_bfloat162 hv1; hv1.x = h2; hv1.y = h3;
    __nv_bfloat162 lv0; lv0.x = l0; lv0.y = l1;
    __nv_bfloat162 lv1; lv1.x = l2; lv1.y = l3;
    *(uint2*)(hi + i) = make_uint2(*(uint32_t*)&hv0, *(uint32_t*)&hv1);
    *(uint2*)(lo + i) = make_uint2(*(uint32_t*)&lv0, *(uint32_t*)&lv1);
}

// ---------------------------------------------------------------------------
// mma.sync bf16 split-GEMM (validated R4/R7 @ rel_err ~7e-6)
// ---------------------------------------------------------------------------
#define TPAD 40
#define TILE_B (128 * TPAD * 2)
#define STAGE_B (4 * TILE_B)
#define GSMEM (2 * STAGE_B)

__device__ __forceinline__ void gemm_issue(uint32_t sb, int stage, const __nv_bfloat16* const* srcs,
                                           int K, int kt, int tid)
{
    uint32_t stbase = sb + stage * STAGE_B;
    const int k0 = kt * 32;
#pragma unroll
    for (int t = 0; t < 4; t++) {
        const __nv_bfloat16* s = srcs[t] + k0;
#pragma unroll
        for (int i = 0; i < 2; i++) {
            int idx = tid + i * 256;
            int row = idx >> 2, ch = idx & 3;
            cp16(stbase + t * TILE_B + row * (TPAD * 2) + ch * 16,
                 s + (size_t)row * K + ch * 8);
        }
    }
    CP_COMMIT();
}

__global__ __launch_bounds__(256, 1)
void gemm_mma(const __nv_bfloat16* __restrict__ Ahi, const __nv_bfloat16* __restrict__ Alo,
              const __nv_bfloat16* __restrict__ Whi, const __nv_bfloat16* __restrict__ Wlo,
              const float* __restrict__ bias, float* __restrict__ Cf,
              __nv_bfloat16* __restrict__ Chi, __nv_bfloat16* __restrict__ Clo,
              int M, int N, int K, int relu)
{
    extern __shared__ char sm[];
    const uint32_t sb = smem_u32(sm);
    const int tid = threadIdx.x;
    const int wid = tid >> 5;
    const int lane = tid & 31;
    const int bm = blockIdx.y * 128;
    const int bn = blockIdx.x * 128;
    const int wm = (wid & 1) * 64;
    const int wn = (wid >> 1) * 32;

    const __nv_bfloat16* srcs[4];
    srcs[0] = Ahi + (size_t)bm * K;
    srcs[1] = Alo + (size_t)bm * K;
    srcs[2] = Whi + (size_t)bn * K;
    srcs[3] = Wlo + (size_t)bn * K;

    float acc[4][4][4];
#pragma unroll
    for (int i = 0; i < 4; i++)
#pragma unroll
        for (int j = 0; j < 4; j++)
#pragma unroll
            for (int r = 0; r < 4; r++) acc[i][j][r] = 0.f;

    const int KT = K >> 5;
    gemm_issue(sb, 0, srcs, K, 0, tid);
    gemm_issue(sb, 1, srcs, K, 1, tid);

    const int a_lofs = ((((lane >> 3) & 1) << 3) + (lane & 7)) * (TPAD * 2) + ((lane >> 4) << 4);
    const int b_lofs = ((((lane >> 4) & 1) << 3) + (lane & 7)) * (TPAD * 2) + (((lane >> 3) & 1) << 4);

    for (int kt = 0; kt < KT; kt++) {
        if (kt == KT - 1) { CP_WAIT0(); } else { CP_WAIT1(); }
        __syncthreads();
        const uint32_t base = sb + (kt & 1) * STAGE_B;

#pragma unroll
        for (int ks = 0; ks < 2; ks++) {
            uint32_t ah[4][4], al[4][4], bh[4][2], bl[4][2];
            const uint32_t aoff = base + (wm)*(TPAD * 2) + ks * 32 + a_lofs;
            const uint32_t boff = base + 2 * TILE_B + (wn)*(TPAD * 2) + ks * 32 + b_lofs;
#pragma unroll
            for (int i = 0; i < 4; i++) {
                LDSM4(ah[i][0], ah[i][1], ah[i][2], ah[i][3], aoff + i * 16 * (TPAD * 2));
                LDSM4(al[i][0], al[i][1], al[i][2], al[i][3], aoff + TILE_B + i * 16 * (TPAD * 2));
            }
#pragma unroll
            for (int g = 0; g < 2; g++) {
                LDSM4(bh[2 * g][0], bh[2 * g][1], bh[2 * g + 1][0], bh[2 * g + 1][1],
                      boff + g * 16 * (TPAD * 2));
                LDSM4(bl[2 * g][0], bl[2 * g][1], bl[2 * g + 1][0], bl[2 * g + 1][1],
                      boff + TILE_B + g * 16 * (TPAD * 2));
            }
#pragma unroll
            for (int i = 0; i < 4; i++)
#pragma unroll
                for (int j = 0; j < 4; j++) MMA16816(acc[i][j], ah[i], bh[j]);
#pragma unroll
            for (int i = 0; i < 4; i++)
#pragma unroll
                for (int j = 0; j < 4; j++) MMA16816(acc[i][j], al[i], bh[j]);
#pragma unroll
            for (int i = 0; i < 4; i++)
#pragma unroll
                for (int j = 0; j < 4; j++) MMA16816(acc[i][j], ah[i], bl[j]);
        }
        __syncthreads();
        if (kt + 2 < KT) gemm_issue(sb, kt & 1, srcs, K, kt + 2, tid);
    }

    const int rr = lane >> 2;
    const int cc = (lane & 3) * 2;
#pragma unroll
    for (int i = 0; i < 4; i++) {
#pragma unroll
        for (int j = 0; j < 4; j++) {
            int r0 = bm + wm + i * 16 + rr;
            int c = bn + wn + j * 8 + cc;
            float b0 = __ldg(bias + c), b1 = __ldg(bias + c + 1);
            float v00 = acc[i][j][0] + b0, v01 = acc[i][j][1] + b1;
            float v10 = acc[i][j][2] + b0, v11 = acc[i][j][3] + b1;
            if (relu) {
                v00 = fmaxf(v00, 0.f); v01 = fmaxf(v01, 0.f);
                v10 = fmaxf(v10, 0.f); v11 = fmaxf(v11, 0.f);
            }
            size_t o0 = (size_t)r0 * N + c;
            size_t o1 = (size_t)(r0 + 8) * N + c;
            if (Cf) {
                *(float2*)(Cf + o0) = make_float2(v00, v01);
                *(float2*)(Cf + o1) = make_float2(v10, v11);
            }
            if (Chi) {
                __nv_bfloat162 h0 = __floats2bfloat162_rn(v00, v01);
                __nv_bfloat162 h1 = __floats2bfloat162_rn(v10, v11);
                __nv_bfloat162 l0 = __floats2bfloat162_rn(v00 - __bfloat162float(h0.x),
                                                          v01 - __bfloat162float(h0.y));
                __nv_bfloat162 l1 = __floats2bfloat162_rn(v10 - __bfloat162float(h1.x),
                                                          v11 - __bfloat162float(h1.y));
                *(__nv_bfloat162*)(Chi + o0) = h0;
                *(__nv_bfloat162*)(Chi + o1) = h1;
                *(__nv_bfloat162*)(Clo + o0) = l0;
                *(__nv_bfloat162*)(Clo + o1) = l1;
            }
        }
    }
}

// ---------------------------------------------------------------------------
// mma.sync flash attention over COMPACTED keys (R7 tiling: 64-q, 128 thr).
// Masked keys contribute exactly 0 (exp underflow) in the reference, so
// iterating only unmasked keys is math-equivalent. Tail slots: scale=0,
// add=-1e9, row index clamped to a valid key (finite values -> exact 0 weight).
// smem layout (pitch 72 bf16 = 144B/row):
//   sQh 0, sQl 9216, sKh 18432, sKl 27648, sVh 36864, sVl 46080, maskSA 55296
// ---------------------------------------------------------------------------
#define APITCHB 144
#define ATT_SMEM (55296 + 512)

__global__ __launch_bounds__(128, 1)
void attention_mma(const __nv_bfloat16* __restrict__ QKVh, const __nv_bfloat16* __restrict__ QKVl,
                   const float* __restrict__ maskSA, const int* __restrict__ cidx,
                   const int* __restrict__ nb,
                   __nv_bfloat16* __restrict__ Ohi, __nv_bfloat16* __restrict__ Olo)
{
    extern __shared__ char ab[];
    const uint32_t sb = smem_u32(ab);
    const int b = blockIdx.z, h = blockIdx.y, q0 = blockIdx.x * 64;
    const int tid = threadIdx.x, wid = tid >> 5, lane = tid & 31;

    const uint32_t sQh = sb, sQl = sb + 9216;
    const uint32_t sKh = sb + 18432, sKl = sb + 27648;
    const uint32_t sVh = sb + 36864, sVl = sb + 46080;
    const uint32_t sMsk = sb + 55296;

    const int nkeys = nb[b];
    const int ntiles = (nkeys + 63) >> 6;
    const int* cix = cidx + (size_t)b * SS;

    // --- load Q hi/lo tiles (once) ---
    {
        const size_t rb = ((size_t)b * SS + q0) * QKVN + h * DKV;
#pragma unroll
        for (int i = 0; i < 8; i++) {
            int idx = tid + i * 128;             // 0..1023
            int t = idx >> 9;                    // 0 hi, 1 lo
            int row = (idx >> 3) & 63;
            int ch = idx & 7;
            const __nv_bfloat16* src = (t ? QKVl : QKVh) + rb + (size_t)row * QKVN + ch * 8;
            cp16((t ? sQl : sQh) + row * APITCHB + ch * 16, src);
        }
    }
    CP_COMMIT();

    // per-lane row state: row g = lane>>2, row g+8
    float m0 = -1e30f, m1 = -1e30f, l0 = 0.f, l1 = 0.f;
    float o[8][4];
#pragma unroll
    for (int j = 0; j < 8; j++)
#pragma unroll
        for (int r = 0; r < 4; r++) o[j][r] = 0.f;

    // ldmatrix lane offsets
    const uint32_t a_lofs = (uint32_t)((wid * 16 + (((lane >> 3) & 1) << 3) + (lane & 7)) * APITCHB
                                       + ((lane >> 4) << 4));
    const uint32_t b_lofs = (uint32_t)(((((lane >> 4) & 1) << 3) + (lane & 7)) * APITCHB
                                       + (((lane >> 3) & 1) << 4));
    const uint32_t v_lofs = (uint32_t)((lane & 15) * APITCHB + ((lane >> 4) << 4));

    for (int itl = 0; itl < ntiles; itl++) {
        const int j0 = itl * 64;
        // --- load gathered K/V hi/lo tiles + compacted mask (scale,add) ---
#pragma unroll
        for (int i = 0; i < 16; i++) {
            int idx = tid + i * 128;             // 0..2047
            int t = idx >> 9;                    // 0 Kh, 1 Kl, 2 Vh, 3 Vl
            int row = (idx >> 3) & 63;
            int ch = idx & 7;
            const int grow = cix[j0 + row];      // gathered key row (L1-hot)
            const __nv_bfloat16* base = (t == 0 || t == 2) ? QKVh : QKVl;
            size_t goff = ((size_t)b * SS + grow) * QKVN + 512 + ((t >= 2) ? 512 : 0)
                          + h * DKV + ch * 8;
            uint32_t d = (t == 0 ? sKh : t == 1 ? sKl : t == 2 ? sVh : sVl) + row * APITCHB + ch * 16;
            cp16(d, base + goff);
        }
        if (tid < 32) cp16(sMsk + tid * 16, maskSA + ((size_t)b * SS + j0) * 2 + tid * 4);
        CP_COMMIT();
        CP_WAIT0();
        __syncthreads();

        // --- S = Q K^T (3-pass split) ---
        float s[8][4];
#pragma unroll
        for (int j = 0; j < 8; j++)
#pragma unroll
            for (int r = 0; r < 4; r++) s[j][r] = 0.f;

#pragma unroll
        for (int kc = 0; kc < 4; kc++) {
            uint32_t qh[4], ql[4];
            LDSM4(qh[0], qh[1], qh[2], qh[3], sQh + a_lofs + kc * 32);
            LDSM4(ql[0], ql[1], ql[2], ql[3], sQl + a_lofs + kc * 32);
#pragma unroll
            for (int g = 0; g < 4; g++) {
                uint32_t kh0[2], kh1[2], kl0[2], kl1[2];
                LDSM4(kh0[0], kh0[1], kh1[0], kh1[1], sKh + b_lofs + g * 16 * APITCHB + kc * 32);
                LDSM4(kl0[0], kl0[1], kl1[0], kl1[1], sKl + b_lofs + g * 16 * APITCHB + kc * 32);
                MMA16816(s[2 * g],     qh, kh0);
                MMA16816(s[2 * g],     ql, kh0);
                MMA16816(s[2 * g],     qh, kl0);
                MMA16816(s[2 * g + 1], qh, kh1);
                MMA16816(s[2 * g + 1], ql, kh1);
                MMA16816(s[2 * g + 1], qh, kl1);
            }
        }

        // --- scale + mask: s' = s*scale + add (tail slots -> exactly -1e9) ---
#pragma unroll
        for (int j = 0; j < 8; j++) {
            float4 f = *(const float4*)(ab + 55296 + (j * 8 + (lane & 3) * 2) * 8);
            s[j][0] = fmaf(s[j][0], f.x, f.y);
            s[j][1] = fmaf(s[j][1], f.z, f.w);
            s[j][2] = fmaf(s[j][2], f.x, f.y);
            s[j][3] = fmaf(s[j][3], f.z, f.w);
        }

        // --- online softmax ---
        float mx0 = -1e30f, mx1 = -1e30f;
#pragma unroll
        for (int j = 0; j < 8; j++) {
            mx0 = fmaxf(mx0, fmaxf(s[j][0], s[j][1]));
            mx1 = fmaxf(mx1, fmaxf(s[j][2], s[j][3]));
        }
        mx0 = fmaxf(mx0, __shfl_xor_sync(0xffffffffu, mx0, 1));
        mx0 = fmaxf(mx0, __shfl_xor_sync(0xffffffffu, mx0, 2));
        mx1 = fmaxf(mx1, __shfl_xor_sync(0xffffffffu, mx1, 1));
        mx1 = fmaxf(mx1, __shfl_xor_sync(0xffffffffu, mx1, 2));

        float mn0 = fmaxf(m0, mx0), mn1 = fmaxf(m1, mx1);
        float al0 = __expf(m0 - mn0), al1 = __expf(m1 - mn1);
        float sum0 = 0.f, sum1 = 0.f;
#pragma unroll
        for (int j = 0; j < 8; j++) {
            s[j][0] = __expf(s[j][0] - mn0); sum0 += s[j][0];
            s[j][1] = __expf(s[j][1] - mn0); sum0 += s[j][1];
            s[j][2] = __expf(s[j][2] - mn1); sum1 += s[j][2];
            s[j][3] = __expf(s[j][3] - mn1); sum1 += s[j][3];
        }
        sum0 += __shfl_xor_sync(0xffffffffu, sum0, 1);
        sum0 += __shfl_xor_sync(0xffffffffu, sum0, 2);
        sum1 += __shfl_xor_sync(0xffffffffu, sum1, 1);
        sum1 += __shfl_xor_sync(0xffffffffu, sum1, 2);
        l0 = l0 * al0 + sum0; m0 = mn0;
        l1 = l1 * al1 + sum1; m1 = mn1;
#pragma unroll
        for (int j = 0; j < 8; j++) {
            o[j][0] *= al0; o[j][1] *= al0;
            o[j][2] *= al1; o[j][3] *= al1;
        }

        // --- O += P V (3-pass split; P from accumulators) ---
#pragma unroll
        for (int kc = 0; kc < 4; kc++) {
            uint32_t ph[4], pl[4];
            {
                int j = 2 * kc;
                float h00 = s[j][0],   h01 = s[j][1],   h10 = s[j][2],   h11 = s[j][3];
                float g00 = s[j+1][0], g01 = s[j+1][1], g10 = s[j+1][2], g11 = s[j+1][3];
                ph[0] = pack_bf16x2(h00, h01);
                ph[1] = pack_bf16x2(h10, h11);
                ph[2] = pack_bf16x2(g00, g01);
                ph[3] = pack_bf16x2(g10, g11);
                __nv_bfloat162 t0 = *(__nv_bfloat162*)&ph[0];
                __nv_bfloat162 t1 = *(__nv_bfloat162*)&ph[1];
                __nv_bfloat162 t2 = *(__nv_bfloat162*)&ph[2];
                __nv_bfloat162 t3 = *(__nv_bfloat162*)&ph[3];
                pl[0] = pack_bf16x2(h00 - __bfloat162float(t0.x), h01 - __bfloat162float(t0.y));
                pl[1] = pack_bf16x2(h10 - __bfloat162float(t1.x), h11 - __bfloat162float(t1.y));
                pl[2] = pack_bf16x2(g00 - __bfloat162float(t2.x), g01 - __bfloat162float(t2.y));
                pl[3] = pack_bf16x2(g10 - __bfloat162float(t3.x), g11 - __bfloat162float(t3.y));
            }
#pragma unroll
            for (int p = 0; p < 4; p++) {
                uint32_t vh0[2], vh1[2], vl0[2], vl1[2];
                LDSM4T(vh0[0], vh0[1], vh1[0], vh1[1],
                       sVh + v_lofs + kc * 16 * APITCHB + p * 32);
                LDSM4T(vl0[0], vl0[1], vl1[0], vl1[1],
                       sVl + v_lofs + kc * 16 * APITCHB + p * 32);
                MMA16816(o[2 * p],     ph, vh0);
                MMA16816(o[2 * p],     pl, vh0);
                MMA16816(o[2 * p],     ph, vl0);
                MMA16816(o[2 * p + 1], ph, vh1);
                MMA16816(o[2 * p + 1], pl, vh1);
                MMA16816(o[2 * p + 1], ph, vl1);
            }
        }
        __syncthreads();   // done with K/V/mask smem before next iteration's loads
    }

    // --- epilogue: write bf16 hi/lo of O (batch offset included) ---
    const float inv0 = 1.0f / l0, inv1 = 1.0f / l1;
    const size_t rg = (size_t)b * SS + q0 + wid * 16 + (lane >> 2);
    const int cb = h * DKV + (lane & 3) * 2;
#pragma unroll
    for (int j = 0; j < 8; j++) {
        size_t off0 = rg * DD + cb + j * 8;
        size_t off1 = (rg + 8) * DD + cb + j * 8;
        float v00 = o[j][0] * inv0, v01 = o[j][1] * inv0;
        float v10 = o[j][2] * inv1, v11 = o[j][3] * inv1;
        uint32_t h0 = pack_bf16x2(v00, v01);
        uint32_t h1 = pack_bf16x2(v10, v11);
        __nv_bfloat162 t0 = *(__nv_bfloat162*)&h0;
        __nv_bfloat162 t1 = *(__nv_bfloat162*)&h1;
        uint32_t z0 = pack_bf16x2(v00 - __bfloat162float(t0.x), v01 - __bfloat162float(t0.y));
        uint32_t z1 = pack_bf16x2(v10 - __bfloat162float(t1.x), v11 - __bfloat162float(t1.y));
        *(uint32_t*)(Ohi + off0) = h0;
        *(uint32_t*)(Ohi + off1) = h1;
        *(uint32_t*)(Olo + off0) = z0;
        *(uint32_t*)(Olo + off1) = z1;
    }
}

// ---------------------------------------------------------------------------
// Residual + LayerNorm (unbiased var, scalar gamma/beta), optional bf16 split
// ---------------------------------------------------------------------------
__global__ __launch_bounds__(128)
void ln_add_kernel(const float* __restrict__ X, const float* __restrict__ Z,
                   const float* __restrict__ g, const float* __restrict__ beta,
                   float* __restrict__ Out,
                   __nv_bfloat16* __restrict__ Ohi, __nv_bfloat16* __restrict__ Olo)
{
    __shared__ float red[4];
    const int row = blockIdx.x;
    const int t = threadIdx.x;
    const float4 zv = ((const float4*)(Z + (size_t)row * DD))[t];

    float s = zv.x + zv.y + zv.z + zv.w;
#pragma unroll
    for (int off = 16; off > 0; off >>= 1) s += __shfl_down_sync(0xffffffffu, s, off);
    if ((t & 31) == 0) red[t >> 5] = s;
    __syncthreads();
    float mean = (red[0] + red[1] + red[2] + red[3]) * (1.0f / DD);
    __syncthreads();

    float d0 = zv.x - mean, d1 = zv.y - mean, d2 = zv.z - mean, d3 = zv.w - mean;
    float ss = d0 * d0 + d1 * d1 + d2 * d2 + d3 * d3;
#pragma unroll
    for (int off = 16; off > 0; off >>= 1) ss += __shfl_down_sync(0xffffffffu, ss, off);
    if ((t & 31) == 0) red[t >> 5] = ss;
    __syncthreads();
    float var = (red[0] + red[1] + red[2] + red[3]) * (1.0f / (DD - 1));

    float inv = rsqrtf(var + 1e-6f);
    float gg = *g, bb = *beta;

    const float4 xv = ((const float4*)(X + (size_t)row * DD))[t];
    float4 o;
    o.x = xv.x + gg * d0 * inv + bb;
    o.y = xv.y + gg * d1 * inv + bb;
    o.z = xv.z + gg * d2 * inv + bb;
    o.w = xv.w + gg * d3 * inv + bb;
    ((float4*)(Out + (size_t)row * DD))[t] = o;

    if (Ohi) {
        size_t off = (size_t)row * DD + t * 4;
        __nv_bfloat162 h0 = __floats2bfloat162_rn(o.x, o.y);
        __nv_bfloat162 h1 = __floats2bfloat162_rn(o.z, o.w);
        __nv_bfloat162 l0 = __floats2bfloat162_rn(o.x - __bfloat162float(h0.x),
                                                  o.y - __bfloat162float(h0.y));
        __nv_bfloat162 l1 = __floats2bfloat162_rn(o.z - __bfloat162float(h1.x),
                                                  o.w - __bfloat162float(h1.y));
        *(__nv_bfloat162*)(Ohi + off)     = h0;
        *(__nv_bfloat162*)(Ohi + off + 2) = h1;
        *(__nv_bfloat162*)(Olo + off)     = l0;
        *(__nv_bfloat162*)(Olo + off + 2) = l1;
    }
}

// ---------------------------------------------------------------------------
// Launch
// ---------------------------------------------------------------------------
extern "C" void kernel_launch(void* const* d_in, const int* in_sizes, int n_in,
                              void* d_out, int out_size)
{
    const float* x    = (const float*)d_in[0];
    const void*  mraw = (const void*)d_in[1];
    const float* wq   = (const float*)d_in[2];
    const float* bq   = (const float*)d_in[3];
    const float* wk   = (const float*)d_in[4];
    const float* bk   = (const float*)d_in[5];
    const float* wv   = (const float*)d_in[6];
    const float* bv   = (const float*)d_in[7];
    const float* wo   = (const float*)d_in[8];
    const float* bo   = (const float*)d_in[9];
    const float* w1   = (const float*)d_in[10];
    const float* b1   = (const float*)d_in[11];
    const float* w2   = (const float*)d_in[12];
    const float* b2   = (const float*)d_in[13];
    const float* g1   = (const float*)d_in[14];
    const float* be1  = (const float*)d_in[15];
    const float* g2   = (const float*)d_in[16];
    const float* be2  = (const float*)d_in[17];
    float* out = (float*)d_out;

    float *pO, *pY, *pBias, *pMSA;
    __nv_bfloat16 *pQKVh, *pQKVl, *pAhi, *pAlo, *pFhi, *pFlo, *pWhi, *pWlo;
    int *pMF, *pCidx, *pNb;
    cudaGetSymbolAddress((void**)&pO, g_O);
    cudaGetSymbolAddress((void**)&pY, g_Y);
    cudaGetSymbolAddress((void**)&pQKVh, g_QKVh);
    cudaGetSymbolAddress((void**)&pQKVl, g_QKVl);
    cudaGetSymbolAddress((void**)&pAhi, g_Ahi);
    cudaGetSymbolAddress((void**)&pAlo, g_Alo);
    cudaGetSymbolAddress((void**)&pFhi, g_Fhi);
    cudaGetSymbolAddress((void**)&pFlo, g_Flo);
    cudaGetSymbolAddress((void**)&pWhi, g_Whi);
    cudaGetSymbolAddress((void**)&pWlo, g_Wlo);
    cudaGetSymbolAddress((void**)&pBias, g_biasQKV);
    cudaGetSymbolAddress((void**)&pMSA, g_maskSA);
    cudaGetSymbolAddress((void**)&pCidx, g_cidx);
    cudaGetSymbolAddress((void**)&pNb, g_nb);
    cudaGetSymbolAddress((void**)&pMF, g_mflag);

    cudaFuncSetAttribute(gemm_mma, cudaFuncAttributeMaxDynamicSharedMemorySize, GSMEM);
    cudaFuncSetAttribute(attention_mma, cudaFuncAttributeMaxDynamicSharedMemorySize, ATT_SMEM);

    // mask compaction + bias prep
    detect_mask_kernel<<<1, 256>>>(mraw, pMF);
    compact_mask_kernel<<<BB, 512>>>(mraw, pMF, pCidx, pMSA, pNb);
    concat_bias_kernel<<<(QKVN + 255) / 256, 256>>>(bq, bk, bv, pBias);

    // weight splits
    split_bf16_kernel<<<(DD * DD) / 1024, 256>>>(wq, pWhi + WOFF_QKV,            pWlo + WOFF_QKV,            DD * DD);
    split_bf16_kernel<<<(DD * DD) / 1024, 256>>>(wk, pWhi + WOFF_QKV + DD * DD,  pWlo + WOFF_QKV + DD * DD,  DD * DD);
    split_bf16_kernel<<<(DD * DD) / 1024, 256>>>(wv, pWhi + WOFF_QKV + 2*DD*DD,  pWlo + WOFF_QKV + 2*DD*DD,  DD * DD);
    split_bf16_kernel<<<(DD * DD) / 1024, 256>>>(wo, pWhi + WOFF_O,  pWlo + WOFF_O,  DD * DD);
    split_bf16_kernel<<<(DFF * DD) / 1024, 256>>>(w1, pWhi + WOFF_1, pWlo + WOFF_1, DFF * DD);
    split_bf16_kernel<<<(DD * DFF) / 1024, 256>>>(w2, pWhi + WOFF_2, pWlo + WOFF_2, DD * DFF);

    // x split
    split_bf16_kernel<<<(MM * DD) / 1024, 256>>>(x, pAhi, pAlo, MM * DD);

    // fused QKV projection -> bf16 hi/lo only
    dim3 gQKV(QKVN / 128, MM / 128);
    gemm_mma<<<gQKV, 256, GSMEM>>>(pAhi, pAlo, pWhi + WOFF_QKV, pWlo + WOFF_QKV,
                                   pBias, ((float*)0), pQKVh, pQKVl,
                                   MM, QKVN, DD, 0);

    // attention over compacted keys (tensor-core, R7 tiling)
    dim3 gAtt(SS / 64, HH, BB);
    attention_mma<<<gAtt, 128, ATT_SMEM>>>(pQKVh, pQKVl, pMSA, pCidx, pNb, pAhi, pAlo);

    // WO projection -> fp32 pO
    dim3 gProj(DD / 128, MM / 128);
    gemm_mma<<<gProj, 256, GSMEM>>>(pAhi, pAlo, pWhi + WOFF_O, pWlo + WOFF_O,
                                    bo, pO, ((__nv_bfloat16*)0), ((__nv_bfloat16*)0),
                                    MM, DD, DD, 0);

    // residual 1 + LN -> Y (fp32) + split into pAhi/pAlo
    ln_add_kernel<<<MM, 128>>>(x, pO, g1, be1, pY, pAhi, pAlo);

    // FFN1: relu, bf16 split out only
    dim3 gFF1(DFF / 128, MM / 128);
    gemm_mma<<<gFF1, 256, GSMEM>>>(pAhi, pAlo, pWhi + WOFF_1, pWlo + WOFF_1,
                                   b1, ((float*)0), pFhi, pFlo,
                                   MM, DFF, DD, 1);

    // FFN2 -> fp32 pO
    gemm_mma<<<gProj, 256, GSMEM>>>(pFhi, pFlo, pWhi + WOFF_2, pWlo + WOFF_2,
                                    b2, pO, ((__nv_bfloat16*)0), ((__nv_bfloat16*)0),
                                    MM, DD, DFF, 0);

    // residual 2 + LN -> out
    ln_add_kernel<<<MM, 128>>>(pY, pO, g2, be2, out, ((__nv_bfloat16*)0), ((__nv_bfloat16*)0));
}

// round 16
// speedup vs baseline: 1.3460x; 1.1173x over previous
#include <cuda_runtime.h>
#include <cuda_bf16.h>
#include <math.h>
#include <stdint.h>

// Problem dims
#define BB   4
#define SS   2048
#define DD   512
#define HH   8
#define DKV  64
#define DFF  2048
#define MM   (BB * SS)     // 8192 rows
#define QKVN 1536          // fused Q|K|V output width

// ---------------------------------------------------------------------------
// Scratch (device globals — no allocation allowed)
// ---------------------------------------------------------------------------
__device__ __align__(256) float g_O[MM * DD];       // gemm fp32 out (WO / FFN2)
__device__ __align__(256) float g_Y[MM * DD];       // residual-1 output
__device__ __align__(256) __nv_bfloat16 g_QKVh[MM * QKVN];
__device__ __align__(256) __nv_bfloat16 g_QKVl[MM * QKVN];
__device__ __align__(256) __nv_bfloat16 g_Ahi[MM * DD];   // activation splits [M,512]
__device__ __align__(256) __nv_bfloat16 g_Alo[MM * DD];
__device__ __align__(256) __nv_bfloat16 g_Fhi[MM * DFF];  // FFN hidden splits
__device__ __align__(256) __nv_bfloat16 g_Flo[MM * DFF];
// weights [N,K] row-major, concatenated: qkv rows 0..1535 (K=512), wo, w1, w2
#define WOFF_QKV 0
#define WOFF_O   (QKVN * DD)
#define WOFF_1   (WOFF_O + DD * DD)
#define WOFF_2   (WOFF_1 + DFF * DD)
#define WTOT     (WOFF_2 + DD * DFF)
__device__ __align__(256) __nv_bfloat16 g_Whi[WTOT];
__device__ __align__(256) __nv_bfloat16 g_Wlo[WTOT];
__device__ float g_biasQKV[QKVN];
__device__ float g_maskSA[BB * SS * 2];   // compacted (scale, add) per key slot
__device__ int   g_cidx[BB * SS];         // compacted key indices per batch
__device__ int   g_nb[BB];                // unmasked key count per batch
__device__ int   g_mflag[1];

// ---------------------------------------------------------------------------
// Helpers
// ---------------------------------------------------------------------------
__device__ __forceinline__ uint32_t smem_u32(const void* p) {
    uint32_t a;
    asm("{ .reg .u64 t; cvta.to.shared.u64 t, %1; cvt.u32.u64 %0, t; }" : "=r"(a) : "l"(p));
    return a;
}
__device__ __forceinline__ void cp16(uint32_t d, const void* g) {
    asm volatile("cp.async.cg.shared.global [%0], [%1], 16;" :: "r"(d), "l"(g));
}
#define CP_COMMIT() asm volatile("cp.async.commit_group;" ::: "memory")
#define CP_WAIT0()  asm volatile("cp.async.wait_group 0;" ::: "memory")
#define CP_WAIT1()  asm volatile("cp.async.wait_group 1;" ::: "memory")

#define LDSM4(r0, r1, r2, r3, a) \
    asm volatile("ldmatrix.sync.aligned.m8n8.x4.shared.b16 {%0,%1,%2,%3}, [%4];" \
                 : "=r"(r0), "=r"(r1), "=r"(r2), "=r"(r3) : "r"(a))
#define LDSM4T(r0, r1, r2, r3, a) \
    asm volatile("ldmatrix.sync.aligned.m8n8.x4.trans.shared.b16 {%0,%1,%2,%3}, [%4];" \
                 : "=r"(r0), "=r"(r1), "=r"(r2), "=r"(r3) : "r"(a))

#define MMA16816(d, a, b) \
    asm volatile("mma.sync.aligned.m16n8k16.row.col.f32.bf16.bf16.f32 " \
                 "{%0,%1,%2,%3},{%4,%5,%6,%7},{%8,%9},{%0,%1,%2,%3};" \
                 : "+f"((d)[0]), "+f"((d)[1]), "+f"((d)[2]), "+f"((d)[3]) \
                 : "r"((a)[0]), "r"((a)[1]), "r"((a)[2]), "r"((a)[3]), \
                   "r"((b)[0]), "r"((b)[1]))

__device__ __forceinline__ uint32_t pack_bf16x2(float a, float b) {
    __nv_bfloat162 v = __floats2bfloat162_rn(a, b);
    return *(uint32_t*)&v;
}

// ---------------------------------------------------------------------------
// Mask canonicalization
// ---------------------------------------------------------------------------
__global__ void detect_mask_kernel(const void* __restrict__ m, int* __restrict__ flag)
{
    __shared__ int bad_int, bad_flt;
    if (threadIdx.x == 0) { bad_int = 0; bad_flt = 0; }
    __syncthreads();
    const int* mi = (const int*)m;
    const float* mf = (const float*)m;
    for (int i = threadIdx.x; i < 2048; i += 256) {
        int vi = mi[i];
        if (vi != 0 && vi != 1) bad_int = 1;
        float vf = mf[i];
        if (vf != 0.0f && vf != 1.0f) bad_flt = 1;
    }
    __syncthreads();
    if (threadIdx.x == 0) flag[0] = bad_int ? (bad_flt ? 2 : 1) : 0;
}

// Compact unmasked keys per batch (stable order). One block per batch, 512 thr.
__global__ __launch_bounds__(512)
void compact_mask_kernel(const void* __restrict__ m, const int* __restrict__ flag,
                         int* __restrict__ cidx, float* __restrict__ msa,
                         int* __restrict__ nb)
{
    __shared__ int wsum[16];
    __shared__ int first_s;
    const int b = blockIdx.x;
    const int t = threadIdx.x;
    const int f = flag[0];

    int keep[4];
#pragma unroll
    for (int k = 0; k < 4; k++) {
        int gi = b * SS + t * 4 + k;
        int v;
        if (f == 0)      v = (((const int*)m)[gi] != 0);
        else if (f == 1) v = (((const float*)m)[gi] != 0.0f);
        else             v = (((const unsigned char*)m)[gi] != 0);
        keep[k] = !v;
    }
    int cnt = keep[0] + keep[1] + keep[2] + keep[3];

    int incl = cnt;
#pragma unroll
    for (int off = 1; off < 32; off <<= 1) {
        int nv = __shfl_up_sync(0xffffffffu, incl, off);
        if ((t & 31) >= off) incl += nv;
    }
    if ((t & 31) == 31) wsum[t >> 5] = incl;
    __syncthreads();
    if (t < 16) {
        int v = wsum[t];
#pragma unroll
        for (int off = 1; off < 16; off <<= 1) {
            int nv = __shfl_up_sync(0x0000ffffu, v, off);
            if (t >= off) v += nv;
        }
        wsum[t] = v;
    }
    __syncthreads();
    const int total = wsum[15];
    int pos = ((t >> 5) ? wsum[(t >> 5) - 1] : 0) + incl - cnt;
#pragma unroll
    for (int k = 0; k < 4; k++) {
        if (keep[k]) {
            cidx[b * SS + pos] = t * 4 + k;
            if (pos == 0) first_s = t * 4 + k;
            pos++;
        }
    }
    __syncthreads();
    const int fi = (total > 0) ? first_s : 0;
    for (int p = t; p < SS; p += 512) {
        if (total > 0) {
            if (p >= total) cidx[b * SS + p] = fi;
            msa[(b * SS + p) * 2]     = (p < total) ? 0.125f : 0.0f;
            msa[(b * SS + p) * 2 + 1] = (p < total) ? 0.0f : -1.0e9f;
        } else {
            cidx[b * SS + p] = p;
            msa[(b * SS + p) * 2]     = 0.0f;
            msa[(b * SS + p) * 2 + 1] = 0.0f;
        }
    }
    if (t == 0) nb[b] = (total > 0) ? total : SS;
}

__global__ void concat_bias_kernel(const float* __restrict__ a, const float* __restrict__ b,
                                   const float* __restrict__ c, float* __restrict__ o)
{
    int i = blockIdx.x * 256 + threadIdx.x;
    if (i < 512)          o[i] = a[i];
    else if (i < 1024)    o[i] = b[i - 512];
    else if (i < QKVN)    o[i] = c[i - 1024];
}

// ---------------------------------------------------------------------------
// fp32 -> bf16 hi/lo split
// ---------------------------------------------------------------------------
__global__ __launch_bounds__(256)
void split_bf16_kernel(const float* __restrict__ in, __nv_bfloat16* __restrict__ hi,
                       __nv_bfloat16* __restrict__ lo, int n)
{
    int i = (blockIdx.x * 256 + threadIdx.x) * 4;
    if (i >= n) return;
    float4 v = *(const float4*)(in + i);
    __nv_bfloat16 h0 = __float2bfloat16_rn(v.x);
    __nv_bfloat16 h1 = __float2bfloat16_rn(v.y);
    __nv_bfloat16 h2 = __float2bfloat16_rn(v.z);
    __nv_bfloat16 h3 = __float2bfloat16_rn(v.w);
    __nv_bfloat16 l0 = __float2bfloat16_rn(v.x - __bfloat162float(h0));
    __nv_bfloat16 l1 = __float2bfloat16_rn(v.y - __bfloat162float(h1));
    __nv_bfloat16 l2 = __float2bfloat16_rn(v.z - __bfloat162float(h2));
    __nv_bfloat16 l3 = __float2bfloat16_rn(v.w - __bfloat162float(h3));
    __nv_bfloat162 hv0; hv0.x = h0; hv0.y = h1;
    __nv_bfloat162 hv1; hv1.x = h2; hv1.y = h3;
    __nv_bfloat162 lv0; lv0.x = l0; lv0.y = l1;
    __nv_bfloat162 lv1; lv1.x = l2; lv1.y = l3;
    *(uint2*)(hi + i) = make_uint2(*(uint32_t*)&hv0, *(uint32_t*)&hv1);
    *(uint2*)(lo + i) = make_uint2(*(uint32_t*)&lv0, *(uint32_t*)&lv1);
}

// ---------------------------------------------------------------------------
// mma.sync bf16 split-GEMM. R13-16 change: allow 2 CTAs/SM (launch_bounds 256,2)
// to hide sync/wait bubbles and halve tail-wave quantization.
// ---------------------------------------------------------------------------
#define TPAD 40
#define TILE_B (128 * TPAD * 2)
#define STAGE_B (4 * TILE_B)
#define GSMEM (2 * STAGE_B)

__device__ __forceinline__ void gemm_issue(uint32_t sb, int stage, const __nv_bfloat16* const* srcs,
                                           int K, int kt, int tid)
{
    uint32_t stbase = sb + stage * STAGE_B;
    const int k0 = kt * 32;
#pragma unroll
    for (int t = 0; t < 4; t++) {
        const __nv_bfloat16* s = srcs[t] + k0;
#pragma unroll
        for (int i = 0; i < 2; i++) {
            int idx = tid + i * 256;
            int row = idx >> 2, ch = idx & 3;
            cp16(stbase + t * TILE_B + row * (TPAD * 2) + ch * 16,
                 s + (size_t)row * K + ch * 8);
        }
    }
    CP_COMMIT();
}

__global__ __launch_bounds__(256, 2)
void gemm_mma(const __nv_bfloat16* __restrict__ Ahi, const __nv_bfloat16* __restrict__ Alo,
              const __nv_bfloat16* __restrict__ Whi, const __nv_bfloat16* __restrict__ Wlo,
              const float* __restrict__ bias, float* __restrict__ Cf,
              __nv_bfloat16* __restrict__ Chi, __nv_bfloat16* __restrict__ Clo,
              int M, int N, int K, int relu)
{
    extern __shared__ char sm[];
    const uint32_t sb = smem_u32(sm);
    const int tid = threadIdx.x;
    const int wid = tid >> 5;
    const int lane = tid & 31;
    const int bm = blockIdx.y * 128;
    const int bn = blockIdx.x * 128;
    const int wm = (wid & 1) * 64;
    const int wn = (wid >> 1) * 32;

    const __nv_bfloat16* srcs[4];
    srcs[0] = Ahi + (size_t)bm * K;
    srcs[1] = Alo + (size_t)bm * K;
    srcs[2] = Whi + (size_t)bn * K;
    srcs[3] = Wlo + (size_t)bn * K;

    float acc[4][4][4];
#pragma unroll
    for (int i = 0; i < 4; i++)
#pragma unroll
        for (int j = 0; j < 4; j++)
#pragma unroll
            for (int r = 0; r < 4; r++) acc[i][j][r] = 0.f;

    const int KT = K >> 5;
    gemm_issue(sb, 0, srcs, K, 0, tid);
    gemm_issue(sb, 1, srcs, K, 1, tid);

    const int a_lofs = ((((lane >> 3) & 1) << 3) + (lane & 7)) * (TPAD * 2) + ((lane >> 4) << 4);
    const int b_lofs = ((((lane >> 4) & 1) << 3) + (lane & 7)) * (TPAD * 2) + (((lane >> 3) & 1) << 4);

    for (int kt = 0; kt < KT; kt++) {
        if (kt == KT - 1) { CP_WAIT0(); } else { CP_WAIT1(); }
        __syncthreads();
        const uint32_t base = sb + (kt & 1) * STAGE_B;

#pragma unroll
        for (int ks = 0; ks < 2; ks++) {
            uint32_t ah[4][4], al[4][4], bh[4][2], bl[4][2];
            const uint32_t aoff = base + (wm)*(TPAD * 2) + ks * 32 + a_lofs;
            const uint32_t boff = base + 2 * TILE_B + (wn)*(TPAD * 2) + ks * 32 + b_lofs;
#pragma unroll
            for (int i = 0; i < 4; i++) {
                LDSM4(ah[i][0], ah[i][1], ah[i][2], ah[i][3], aoff + i * 16 * (TPAD * 2));
                LDSM4(al[i][0], al[i][1], al[i][2], al[i][3], aoff + TILE_B + i * 16 * (TPAD * 2));
            }
#pragma unroll
            for (int g = 0; g < 2; g++) {
                LDSM4(bh[2 * g][0], bh[2 * g][1], bh[2 * g + 1][0], bh[2 * g + 1][1],
                      boff + g * 16 * (TPAD * 2));
                LDSM4(bl[2 * g][0], bl[2 * g][1], bl[2 * g + 1][0], bl[2 * g + 1][1],
                      boff + TILE_B + g * 16 * (TPAD * 2));
            }
#pragma unroll
            for (int i = 0; i < 4; i++)
#pragma unroll
                for (int j = 0; j < 4; j++) MMA16816(acc[i][j], ah[i], bh[j]);
#pragma unroll
            for (int i = 0; i < 4; i++)
#pragma unroll
                for (int j = 0; j < 4; j++) MMA16816(acc[i][j], al[i], bh[j]);
#pragma unroll
            for (int i = 0; i < 4; i++)
#pragma unroll
                for (int j = 0; j < 4; j++) MMA16816(acc[i][j], ah[i], bl[j]);
        }
        __syncthreads();
        if (kt + 2 < KT) gemm_issue(sb, kt & 1, srcs, K, kt + 2, tid);
    }

    const int rr = lane >> 2;
    const int cc = (lane & 3) * 2;
#pragma unroll
    for (int i = 0; i < 4; i++) {
#pragma unroll
        for (int j = 0; j < 4; j++) {
            int r0 = bm + wm + i * 16 + rr;
            int c = bn + wn + j * 8 + cc;
            float b0 = __ldg(bias + c), b1 = __ldg(bias + c + 1);
            float v00 = acc[i][j][0] + b0, v01 = acc[i][j][1] + b1;
            float v10 = acc[i][j][2] + b0, v11 = acc[i][j][3] + b1;
            if (relu) {
                v00 = fmaxf(v00, 0.f); v01 = fmaxf(v01, 0.f);
                v10 = fmaxf(v10, 0.f); v11 = fmaxf(v11, 0.f);
            }
            size_t o0 = (size_t)r0 * N + c;
            size_t o1 = (size_t)(r0 + 8) * N + c;
            if (Cf) {
                *(float2*)(Cf + o0) = make_float2(v00, v01);
                *(float2*)(Cf + o1) = make_float2(v10, v11);
            }
            if (Chi) {
                __nv_bfloat162 h0 = __floats2bfloat162_rn(v00, v01);
                __nv_bfloat162 h1 = __floats2bfloat162_rn(v10, v11);
                __nv_bfloat162 l0 = __floats2bfloat162_rn(v00 - __bfloat162float(h0.x),
                                                          v01 - __bfloat162float(h0.y));
                __nv_bfloat162 l1 = __floats2bfloat162_rn(v10 - __bfloat162float(h1.x),
                                                          v11 - __bfloat162float(h1.y));
                *(__nv_bfloat162*)(Chi + o0) = h0;
                *(__nv_bfloat162*)(Chi + o1) = h1;
                *(__nv_bfloat162*)(Clo + o0) = l0;
                *(__nv_bfloat162*)(Clo + o1) = l1;
            }
        }
    }
}

// ---------------------------------------------------------------------------
// mma.sync flash attention over COMPACTED keys (validated R12 @ 7.26e-6).
// smem layout (pitch 72 bf16 = 144B/row):
//   sQh 0, sQl 9216, sKh 18432, sKl 27648, sVh 36864, sVl 46080, maskSA 55296
// ---------------------------------------------------------------------------
#define APITCHB 144
#define ATT_SMEM (55296 + 512)

__global__ __launch_bounds__(128, 1)
void attention_mma(const __nv_bfloat16* __restrict__ QKVh, const __nv_bfloat16* __restrict__ QKVl,
                   const float* __restrict__ maskSA, const int* __restrict__ cidx,
                   const int* __restrict__ nb,
                   __nv_bfloat16* __restrict__ Ohi, __nv_bfloat16* __restrict__ Olo)
{
    extern __shared__ char ab[];
    const uint32_t sb = smem_u32(ab);
    const int b = blockIdx.z, h = blockIdx.y, q0 = blockIdx.x * 64;
    const int tid = threadIdx.x, wid = tid >> 5, lane = tid & 31;

    const uint32_t sQh = sb, sQl = sb + 9216;
    const uint32_t sKh = sb + 18432, sKl = sb + 27648;
    const uint32_t sVh = sb + 36864, sVl = sb + 46080;
    const uint32_t sMsk = sb + 55296;

    const int nkeys = nb[b];
    const int ntiles = (nkeys + 63) >> 6;
    const int* cix = cidx + (size_t)b * SS;

    // --- load Q hi/lo tiles (once) ---
    {
        const size_t rb = ((size_t)b * SS + q0) * QKVN + h * DKV;
#pragma unroll
        for (int i = 0; i < 8; i++) {
            int idx = tid + i * 128;             // 0..1023
            int t = idx >> 9;                    // 0 hi, 1 lo
            int row = (idx >> 3) & 63;
            int ch = idx & 7;
            const __nv_bfloat16* src = (t ? QKVl : QKVh) + rb + (size_t)row * QKVN + ch * 8;
            cp16((t ? sQl : sQh) + row * APITCHB + ch * 16, src);
        }
    }
    CP_COMMIT();

    // per-lane row state: row g = lane>>2, row g+8
    float m0 = -1e30f, m1 = -1e30f, l0 = 0.f, l1 = 0.f;
    float o[8][4];
#pragma unroll
    for (int j = 0; j < 8; j++)
#pragma unroll
        for (int r = 0; r < 4; r++) o[j][r] = 0.f;

    // ldmatrix lane offsets
    const uint32_t a_lofs = (uint32_t)((wid * 16 + (((lane >> 3) & 1) << 3) + (lane & 7)) * APITCHB
                                       + ((lane >> 4) << 4));
    const uint32_t b_lofs = (uint32_t)(((((lane >> 4) & 1) << 3) + (lane & 7)) * APITCHB
                                       + (((lane >> 3) & 1) << 4));
    const uint32_t v_lofs = (uint32_t)((lane & 15) * APITCHB + ((lane >> 4) << 4));

    for (int itl = 0; itl < ntiles; itl++) {
        const int j0 = itl * 64;
        // --- load gathered K/V hi/lo tiles + compacted mask (scale,add) ---
#pragma unroll
        for (int i = 0; i < 16; i++) {
            int idx = tid + i * 128;             // 0..2047
            int t = idx >> 9;                    // 0 Kh, 1 Kl, 2 Vh, 3 Vl
            int row = (idx >> 3) & 63;
            int ch = idx & 7;
            const int grow = cix[j0 + row];      // gathered key row (L1-hot)
            const __nv_bfloat16* base = (t == 0 || t == 2) ? QKVh : QKVl;
            size_t goff = ((size_t)b * SS + grow) * QKVN + 512 + ((t >= 2) ? 512 : 0)
                          + h * DKV + ch * 8;
            uint32_t d = (t == 0 ? sKh : t == 1 ? sKl : t == 2 ? sVh : sVl) + row * APITCHB + ch * 16;
            cp16(d, base + goff);
        }
        if (tid < 32) cp16(sMsk + tid * 16, maskSA + ((size_t)b * SS + j0) * 2 + tid * 4);
        CP_COMMIT();
        CP_WAIT0();
        __syncthreads();

        // --- S = Q K^T (3-pass split) ---
        float s[8][4];
#pragma unroll
        for (int j = 0; j < 8; j++)
#pragma unroll
            for (int r = 0; r < 4; r++) s[j][r] = 0.f;

#pragma unroll
        for (int kc = 0; kc < 4; kc++) {
            uint32_t qh[4], ql[4];
            LDSM4(qh[0], qh[1], qh[2], qh[3], sQh + a_lofs + kc * 32);
            LDSM4(ql[0], ql[1], ql[2], ql[3], sQl + a_lofs + kc * 32);
#pragma unroll
            for (int g = 0; g < 4; g++) {
                uint32_t kh0[2], kh1[2], kl0[2], kl1[2];
                LDSM4(kh0[0], kh0[1], kh1[0], kh1[1], sKh + b_lofs + g * 16 * APITCHB + kc * 32);
                LDSM4(kl0[0], kl0[1], kl1[0], kl1[1], sKl + b_lofs + g * 16 * APITCHB + kc * 32);
                MMA16816(s[2 * g],     qh, kh0);
                MMA16816(s[2 * g],     ql, kh0);
                MMA16816(s[2 * g],     qh, kl0);
                MMA16816(s[2 * g + 1], qh, kh1);
                MMA16816(s[2 * g + 1], ql, kh1);
                MMA16816(s[2 * g + 1], qh, kl1);
            }
        }

        // --- scale + mask: s' = s*scale + add (tail slots -> exactly -1e9) ---
#pragma unroll
        for (int j = 0; j < 8; j++) {
            float4 f = *(const float4*)(ab + 55296 + (j * 8 + (lane & 3) * 2) * 8);
            s[j][0] = fmaf(s[j][0], f.x, f.y);
            s[j][1] = fmaf(s[j][1], f.z, f.w);
            s[j][2] = fmaf(s[j][2], f.x, f.y);
            s[j][3] = fmaf(s[j][3], f.z, f.w);
        }

        // --- online softmax ---
        float mx0 = -1e30f, mx1 = -1e30f;
#pragma unroll
        for (int j = 0; j < 8; j++) {
            mx0 = fmaxf(mx0, fmaxf(s[j][0], s[j][1]));
            mx1 = fmaxf(mx1, fmaxf(s[j][2], s[j][3]));
        }
        mx0 = fmaxf(mx0, __shfl_xor_sync(0xffffffffu, mx0, 1));
        mx0 = fmaxf(mx0, __shfl_xor_sync(0xffffffffu, mx0, 2));
        mx1 = fmaxf(mx1, __shfl_xor_sync(0xffffffffu, mx1, 1));
        mx1 = fmaxf(mx1, __shfl_xor_sync(0xffffffffu, mx1, 2));

        float mn0 = fmaxf(m0, mx0), mn1 = fmaxf(m1, mx1);
        float al0 = __expf(m0 - mn0), al1 = __expf(m1 - mn1);
        float sum0 = 0.f, sum1 = 0.f;
#pragma unroll
        for (int j = 0; j < 8; j++) {
            s[j][0] = __expf(s[j][0] - mn0); sum0 += s[j][0];
            s[j][1] = __expf(s[j][1] - mn0); sum0 += s[j][1];
            s[j][2] = __expf(s[j][2] - mn1); sum1 += s[j][2];
            s[j][3] = __expf(s[j][3] - mn1); sum1 += s[j][3];
        }
        sum0 += __shfl_xor_sync(0xffffffffu, sum0, 1);
        sum0 += __shfl_xor_sync(0xffffffffu, sum0, 2);
        sum1 += __shfl_xor_sync(0xffffffffu, sum1, 1);
        sum1 += __shfl_xor_sync(0xffffffffu, sum1, 2);
        l0 = l0 * al0 + sum0; m0 = mn0;
        l1 = l1 * al1 + sum1; m1 = mn1;
#pragma unroll
        for (int j = 0; j < 8; j++) {
            o[j][0] *= al0; o[j][1] *= al0;
            o[j][2] *= al1; o[j][3] *= al1;
        }

        // --- O += P V (3-pass split; P from accumulators) ---
#pragma unroll
        for (int kc = 0; kc < 4; kc++) {
            uint32_t ph[4], pl[4];
            {
                int j = 2 * kc;
                float h00 = s[j][0],   h01 = s[j][1],   h10 = s[j][2],   h11 = s[j][3];
                float g00 = s[j+1][0], g01 = s[j+1][1], g10 = s[j+1][2], g11 = s[j+1][3];
                ph[0] = pack_bf16x2(h00, h01);
                ph[1] = pack_bf16x2(h10, h11);
                ph[2] = pack_bf16x2(g00, g01);
                ph[3] = pack_bf16x2(g10, g11);
                __nv_bfloat162 t0 = *(__nv_bfloat162*)&ph[0];
                __nv_bfloat162 t1 = *(__nv_bfloat162*)&ph[1];
                __nv_bfloat162 t2 = *(__nv_bfloat162*)&ph[2];
                __nv_bfloat162 t3 = *(__nv_bfloat162*)&ph[3];
                pl[0] = pack_bf16x2(h00 - __bfloat162float(t0.x), h01 - __bfloat162float(t0.y));
                pl[1] = pack_bf16x2(h10 - __bfloat162float(t1.x), h11 - __bfloat162float(t1.y));
                pl[2] = pack_bf16x2(g00 - __bfloat162float(t2.x), g01 - __bfloat162float(t2.y));
                pl[3] = pack_bf16x2(g10 - __bfloat162float(t3.x), g11 - __bfloat162float(t3.y));
            }
#pragma unroll
            for (int p = 0; p < 4; p++) {
                uint32_t vh0[2], vh1[2], vl0[2], vl1[2];
                LDSM4T(vh0[0], vh0[1], vh1[0], vh1[1],
                       sVh + v_lofs + kc * 16 * APITCHB + p * 32);
                LDSM4T(vl0[0], vl0[1], vl1[0], vl1[1],
                       sVl + v_lofs + kc * 16 * APITCHB + p * 32);
                MMA16816(o[2 * p],     ph, vh0);
                MMA16816(o[2 * p],     pl, vh0);
                MMA16816(o[2 * p],     ph, vl0);
                MMA16816(o[2 * p + 1], ph, vh1);
                MMA16816(o[2 * p + 1], pl, vh1);
                MMA16816(o[2 * p + 1], ph, vl1);
            }
        }
        __syncthreads();   // done with K/V/mask smem before next iteration's loads
    }

    // --- epilogue: write bf16 hi/lo of O (batch offset included) ---
    const float inv0 = 1.0f / l0, inv1 = 1.0f / l1;
    const size_t rg = (size_t)b * SS + q0 + wid * 16 + (lane >> 2);
    const int cb = h * DKV + (lane & 3) * 2;
#pragma unroll
    for (int j = 0; j < 8; j++) {
        size_t off0 = rg * DD + cb + j * 8;
        size_t off1 = (rg + 8) * DD + cb + j * 8;
        float v00 = o[j][0] * inv0, v01 = o[j][1] * inv0;
        float v10 = o[j][2] * inv1, v11 = o[j][3] * inv1;
        uint32_t h0 = pack_bf16x2(v00, v01);
        uint32_t h1 = pack_bf16x2(v10, v11);
        __nv_bfloat162 t0 = *(__nv_bfloat162*)&h0;
        __nv_bfloat162 t1 = *(__nv_bfloat162*)&h1;
        uint32_t z0 = pack_bf16x2(v00 - __bfloat162float(t0.x), v01 - __bfloat162float(t0.y));
        uint32_t z1 = pack_bf16x2(v10 - __bfloat162float(t1.x), v11 - __bfloat162float(t1.y));
        *(uint32_t*)(Ohi + off0) = h0;
        *(uint32_t*)(Ohi + off1) = h1;
        *(uint32_t*)(Olo + off0) = z0;
        *(uint32_t*)(Olo + off1) = z1;
    }
}

// ---------------------------------------------------------------------------
// Residual + LayerNorm (unbiased var, scalar gamma/beta), optional bf16 split
// ---------------------------------------------------------------------------
__global__ __launch_bounds__(128)
void ln_add_kernel(const float* __restrict__ X, const float* __restrict__ Z,
                   const float* __restrict__ g, const float* __restrict__ beta,
                   float* __restrict__ Out,
                   __nv_bfloat16* __restrict__ Ohi, __nv_bfloat16* __restrict__ Olo)
{
    __shared__ float red[4];
    const int row = blockIdx.x;
    const int t = threadIdx.x;
    const float4 zv = ((const float4*)(Z + (size_t)row * DD))[t];

    float s = zv.x + zv.y + zv.z + zv.w;
#pragma unroll
    for (int off = 16; off > 0; off >>= 1) s += __shfl_down_sync(0xffffffffu, s, off);
    if ((t & 31) == 0) red[t >> 5] = s;
    __syncthreads();
    float mean = (red[0] + red[1] + red[2] + red[3]) * (1.0f / DD);
    __syncthreads();

    float d0 = zv.x - mean, d1 = zv.y - mean, d2 = zv.z - mean, d3 = zv.w - mean;
    float ss = d0 * d0 + d1 * d1 + d2 * d2 + d3 * d3;
#pragma unroll
    for (int off = 16; off > 0; off >>= 1) ss += __shfl_down_sync(0xffffffffu, ss, off);
    if ((t & 31) == 0) red[t >> 5] = ss;
    __syncthreads();
    float var = (red[0] + red[1] + red[2] + red[3]) * (1.0f / (DD - 1));

    float inv = rsqrtf(var + 1e-6f);
    float gg = *g, bb = *beta;

    const float4 xv = ((const float4*)(X + (size_t)row * DD))[t];
    float4 o;
    o.x = xv.x + gg * d0 * inv + bb;
    o.y = xv.y + gg * d1 * inv + bb;
    o.z = xv.z + gg * d2 * inv + bb;
    o.w = xv.w + gg * d3 * inv + bb;
    ((float4*)(Out + (size_t)row * DD))[t] = o;

    if (Ohi) {
        size_t off = (size_t)row * DD + t * 4;
        __nv_bfloat162 h0 = __floats2bfloat162_rn(o.x, o.y);
        __nv_bfloat162 h1 = __floats2bfloat162_rn(o.z, o.w);
        __nv_bfloat162 l0 = __floats2bfloat162_rn(o.x - __bfloat162float(h0.x),
                                                  o.y - __bfloat162float(h0.y));
        __nv_bfloat162 l1 = __floats2bfloat162_rn(o.z - __bfloat162float(h1.x),
                                                  o.w - __bfloat162float(h1.y));
        *(__nv_bfloat162*)(Ohi + off)     = h0;
        *(__nv_bfloat162*)(Ohi + off + 2) = h1;
        *(__nv_bfloat162*)(Olo + off)     = l0;
        *(__nv_bfloat162*)(Olo + off + 2) = l1;
    }
}

// ---------------------------------------------------------------------------
// Launch
// ---------------------------------------------------------------------------
extern "C" void kernel_launch(void* const* d_in, const int* in_sizes, int n_in,
                              void* d_out, int out_size)
{
    const float* x    = (const float*)d_in[0];
    const void*  mraw = (const void*)d_in[1];
    const float* wq   = (const float*)d_in[2];
    const float* bq   = (const float*)d_in[3];
    const float* wk   = (const float*)d_in[4];
    const float* bk   = (const float*)d_in[5];
    const float* wv   = (const float*)d_in[6];
    const float* bv   = (const float*)d_in[7];
    const float* wo   = (const float*)d_in[8];
    const float* bo   = (const float*)d_in[9];
    const float* w1   = (const float*)d_in[10];
    const float* b1   = (const float*)d_in[11];
    const float* w2   = (const float*)d_in[12];
    const float* b2   = (const float*)d_in[13];
    const float* g1   = (const float*)d_in[14];
    const float* be1  = (const float*)d_in[15];
    const float* g2   = (const float*)d_in[16];
    const float* be2  = (const float*)d_in[17];
    float* out = (float*)d_out;

    float *pO, *pY, *pBias, *pMSA;
    __nv_bfloat16 *pQKVh, *pQKVl, *pAhi, *pAlo, *pFhi, *pFlo, *pWhi, *pWlo;
    int *pMF, *pCidx, *pNb;
    cudaGetSymbolAddress((void**)&pO, g_O);
    cudaGetSymbolAddress((void**)&pY, g_Y);
    cudaGetSymbolAddress((void**)&pQKVh, g_QKVh);
    cudaGetSymbolAddress((void**)&pQKVl, g_QKVl);
    cudaGetSymbolAddress((void**)&pAhi, g_Ahi);
    cudaGetSymbolAddress((void**)&pAlo, g_Alo);
    cudaGetSymbolAddress((void**)&pFhi, g_Fhi);
    cudaGetSymbolAddress((void**)&pFlo, g_Flo);
    cudaGetSymbolAddress((void**)&pWhi, g_Whi);
    cudaGetSymbolAddress((void**)&pWlo, g_Wlo);
    cudaGetSymbolAddress((void**)&pBias, g_biasQKV);
    cudaGetSymbolAddress((void**)&pMSA, g_maskSA);
    cudaGetSymbolAddress((void**)&pCidx, g_cidx);
    cudaGetSymbolAddress((void**)&pNb, g_nb);
    cudaGetSymbolAddress((void**)&pMF, g_mflag);

    cudaFuncSetAttribute(gemm_mma, cudaFuncAttributeMaxDynamicSharedMemorySize, GSMEM);
    cudaFuncSetAttribute(attention_mma, cudaFuncAttributeMaxDynamicSharedMemorySize, ATT_SMEM);

    // mask compaction + bias prep
    detect_mask_kernel<<<1, 256>>>(mraw, pMF);
    compact_mask_kernel<<<BB, 512>>>(mraw, pMF, pCidx, pMSA, pNb);
    concat_bias_kernel<<<(QKVN + 255) / 256, 256>>>(bq, bk, bv, pBias);

    // weight splits
    split_bf16_kernel<<<(DD * DD) / 1024, 256>>>(wq, pWhi + WOFF_QKV,            pWlo + WOFF_QKV,            DD * DD);
    split_bf16_kernel<<<(DD * DD) / 1024, 256>>>(wk, pWhi + WOFF_QKV + DD * DD,  pWlo + WOFF_QKV + DD * DD,  DD * DD);
    split_bf16_kernel<<<(DD * DD) / 1024, 256>>>(wv, pWhi + WOFF_QKV + 2*DD*DD,  pWlo + WOFF_QKV + 2*DD*DD,  DD * DD);
    split_bf16_kernel<<<(DD * DD) / 1024, 256>>>(wo, pWhi + WOFF_O,  pWlo + WOFF_O,  DD * DD);
    split_bf16_kernel<<<(DFF * DD) / 1024, 256>>>(w1, pWhi + WOFF_1, pWlo + WOFF_1, DFF * DD);
    split_bf16_kernel<<<(DD * DFF) / 1024, 256>>>(w2, pWhi + WOFF_2, pWlo + WOFF_2, DD * DFF);

    // x split
    split_bf16_kernel<<<(MM * DD) / 1024, 256>>>(x, pAhi, pAlo, MM * DD);

    // fused QKV projection -> bf16 hi/lo only
    dim3 gQKV(QKVN / 128, MM / 128);
    gemm_mma<<<gQKV, 256, GSMEM>>>(pAhi, pAlo, pWhi + WOFF_QKV, pWlo + WOFF_QKV,
                                   pBias, ((float*)0), pQKVh, pQKVl,
                                   MM, QKVN, DD, 0);

    // attention over compacted keys (tensor-core, R7 tiling)
    dim3 gAtt(SS / 64, HH, BB);
    attention_mma<<<gAtt, 128, ATT_SMEM>>>(pQKVh, pQKVl, pMSA, pCidx, pNb, pAhi, pAlo);

    // WO projection -> fp32 pO
    dim3 gProj(DD / 128, MM / 128);
    gemm_mma<<<gProj, 256, GSMEM>>>(pAhi, pAlo, pWhi + WOFF_O, pWlo + WOFF_O,
                                    bo, pO, ((__nv_bfloat16*)0), ((__nv_bfloat16*)0),
                                    MM, DD, DD, 0);

    // residual 1 + LN -> Y (fp32) + split into pAhi/pAlo
    ln_add_kernel<<<MM, 128>>>(x, pO, g1, be1, pY, pAhi, pAlo);

    // FFN1: relu, bf16 split out only
    dim3 gFF1(DFF / 128, MM / 128);
    gemm_mma<<<gFF1, 256, GSMEM>>>(pAhi, pAlo, pWhi + WOFF_1, pWlo + WOFF_1,
                                   b1, ((float*)0), pFhi, pFlo,
                                   MM, DFF, DD, 1);

    // FFN2 -> fp32 pO
    gemm_mma<<<gProj, 256, GSMEM>>>(pFhi, pFlo, pWhi + WOFF_2, pWlo + WOFF_2,
                                    b2, pO, ((__nv_bfloat16*)0), ((__nv_bfloat16*)0),
                                    MM, DD, DFF, 0);

    // residual 2 + LN -> out
    ln_add_kernel<<<MM, 128>>>(pY, pO, g2, be2, out, ((__nv_bfloat16*)0), ((__nv_bfloat16*)0));
}

// round 17
// speedup vs baseline: 1.3711x; 1.0187x over previous
#include <cuda_runtime.h>
#include <cuda_bf16.h>
#include <math.h>
#include <stdint.h>

// Problem dims
#define BB   4
#define SS   2048
#define DD   512
#define HH   8
#define DKV  64
#define DFF  2048
#define MM   (BB * SS)     // 8192 rows
#define QKVN 1536          // fused Q|K|V output width

// ---------------------------------------------------------------------------
// Scratch (device globals — no allocation allowed)
// ---------------------------------------------------------------------------
__device__ __align__(256) float g_O[MM * DD];       // gemm fp32 out (WO / FFN2)
__device__ __align__(256) float g_Y[MM * DD];       // residual-1 output
__device__ __align__(256) __nv_bfloat16 g_QKVh[MM * QKVN];
__device__ __align__(256) __nv_bfloat16 g_QKVl[MM * QKVN];
__device__ __align__(256) __nv_bfloat16 g_Ahi[MM * DD];   // activation splits [M,512]
__device__ __align__(256) __nv_bfloat16 g_Alo[MM * DD];
__device__ __align__(256) __nv_bfloat16 g_Fhi[MM * DFF];  // FFN hidden splits
__device__ __align__(256) __nv_bfloat16 g_Flo[MM * DFF];
// weights [N,K] row-major, concatenated: qkv rows 0..1535 (K=512), wo, w1, w2
#define WOFF_QKV 0
#define WOFF_O   (QKVN * DD)
#define WOFF_1   (WOFF_O + DD * DD)
#define WOFF_2   (WOFF_1 + DFF * DD)
#define WTOT     (WOFF_2 + DD * DFF)
__device__ __align__(256) __nv_bfloat16 g_Whi[WTOT];
__device__ __align__(256) __nv_bfloat16 g_Wlo[WTOT];
__device__ float g_biasQKV[QKVN];
__device__ float g_maskSA[BB * SS * 2];   // compacted (scale, add) per key slot
__device__ int   g_cidx[BB * SS];         // compacted key indices per batch
__device__ int   g_nb[BB];                // unmasked key count per batch

// ---------------------------------------------------------------------------
// Helpers
// ---------------------------------------------------------------------------
__device__ __forceinline__ uint32_t smem_u32(const void* p) {
    uint32_t a;
    asm("{ .reg .u64 t; cvta.to.shared.u64 t, %1; cvt.u32.u64 %0, t; }" : "=r"(a) : "l"(p));
    return a;
}
__device__ __forceinline__ void cp16(uint32_t d, const void* g) {
    asm volatile("cp.async.cg.shared.global [%0], [%1], 16;" :: "r"(d), "l"(g));
}
#define CP_COMMIT() asm volatile("cp.async.commit_group;" ::: "memory")
#define CP_WAIT0()  asm volatile("cp.async.wait_group 0;" ::: "memory")
#define CP_WAIT1()  asm volatile("cp.async.wait_group 1;" ::: "memory")

#define LDSM4(r0, r1, r2, r3, a) \
    asm volatile("ldmatrix.sync.aligned.m8n8.x4.shared.b16 {%0,%1,%2,%3}, [%4];" \
                 : "=r"(r0), "=r"(r1), "=r"(r2), "=r"(r3) : "r"(a))
#define LDSM4T(r0, r1, r2, r3, a) \
    asm volatile("ldmatrix.sync.aligned.m8n8.x4.trans.shared.b16 {%0,%1,%2,%3}, [%4];" \
                 : "=r"(r0), "=r"(r1), "=r"(r2), "=r"(r3) : "r"(a))

#define MMA16816(d, a, b) \
    asm volatile("mma.sync.aligned.m16n8k16.row.col.f32.bf16.bf16.f32 " \
                 "{%0,%1,%2,%3},{%4,%5,%6,%7},{%8,%9},{%0,%1,%2,%3};" \
                 : "+f"((d)[0]), "+f"((d)[1]), "+f"((d)[2]), "+f"((d)[3]) \
                 : "r"((a)[0]), "r"((a)[1]), "r"((a)[2]), "r"((a)[3]), \
                   "r"((b)[0]), "r"((b)[1]))

__device__ __forceinline__ uint32_t pack_bf16x2(float a, float b) {
    __nv_bfloat162 v = __floats2bfloat162_rn(a, b);
    return *(uint32_t*)&v;
}

// ---------------------------------------------------------------------------
// Mask compaction with self-contained dtype detection (every block scans the
// same first 2048 int-lanes -> identical, deterministic flag). One block per
// batch, 512 thr. Outputs: cidx (compacted indices, tail clamped), msa
// (scale,add) per slot, nb (count). All-masked fallback: identity + (0,0).
// ---------------------------------------------------------------------------
__global__ __launch_bounds__(512)
void compact_mask_kernel(const void* __restrict__ m,
                         int* __restrict__ cidx, float* __restrict__ msa,
                         int* __restrict__ nb)
{
    __shared__ int wsum[16];
    __shared__ int first_s;
    __shared__ int bad_int, bad_flt;
    const int b = blockIdx.x;
    const int t = threadIdx.x;

    // dtype detection (redundant per block; same data -> same result)
    if (t == 0) { bad_int = 0; bad_flt = 0; }
    __syncthreads();
    {
        const int* mi = (const int*)m;
        const float* mf = (const float*)m;
        for (int i = t; i < 2048; i += 512) {
            int vi = mi[i];
            if (vi != 0 && vi != 1) bad_int = 1;
            float vf = mf[i];
            if (vf != 0.0f && vf != 1.0f) bad_flt = 1;
        }
    }
    __syncthreads();
    const int f = bad_int ? (bad_flt ? 2 : 1) : 0;

    int keep[4];
#pragma unroll
    for (int k = 0; k < 4; k++) {
        int gi = b * SS + t * 4 + k;
        int v;
        if (f == 0)      v = (((const int*)m)[gi] != 0);
        else if (f == 1) v = (((const float*)m)[gi] != 0.0f);
        else             v = (((const unsigned char*)m)[gi] != 0);
        keep[k] = !v;
    }
    int cnt = keep[0] + keep[1] + keep[2] + keep[3];

    int incl = cnt;
#pragma unroll
    for (int off = 1; off < 32; off <<= 1) {
        int nv = __shfl_up_sync(0xffffffffu, incl, off);
        if ((t & 31) >= off) incl += nv;
    }
    if ((t & 31) == 31) wsum[t >> 5] = incl;
    __syncthreads();
    if (t < 16) {
        int v = wsum[t];
#pragma unroll
        for (int off = 1; off < 16; off <<= 1) {
            int nv = __shfl_up_sync(0x0000ffffu, v, off);
            if (t >= off) v += nv;
        }
        wsum[t] = v;
    }
    __syncthreads();
    const int total = wsum[15];
    int pos = ((t >> 5) ? wsum[(t >> 5) - 1] : 0) + incl - cnt;
#pragma unroll
    for (int k = 0; k < 4; k++) {
        if (keep[k]) {
            cidx[b * SS + pos] = t * 4 + k;
            if (pos == 0) first_s = t * 4 + k;
            pos++;
        }
    }
    __syncthreads();
    const int fi = (total > 0) ? first_s : 0;
    for (int p = t; p < SS; p += 512) {
        if (total > 0) {
            if (p >= total) cidx[b * SS + p] = fi;
            msa[(b * SS + p) * 2]     = (p < total) ? 0.125f : 0.0f;
            msa[(b * SS + p) * 2 + 1] = (p < total) ? 0.0f : -1.0e9f;
        } else {
            cidx[b * SS + p] = p;
            msa[(b * SS + p) * 2]     = 0.0f;
            msa[(b * SS + p) * 2 + 1] = 0.0f;
        }
    }
    if (t == 0) nb[b] = (total > 0) ? total : SS;
}

// ---------------------------------------------------------------------------
// Fused weight split + bias concat: ONE launch replaces 6 splits + concat.
// Blocks [0,3072): split 3,145,728 weight elements into g_Whi/g_Wlo
//   (dst layout qkv|wo|w1|w2 is contiguous; range bounds are multiples of
//    1024 so a float4 never straddles two source tensors).
// Blocks [3072,3078): concat bq|bk|bv into biasQKV (256 elts per block).
// ---------------------------------------------------------------------------
__device__ __forceinline__ void split4_store(const float* src, __nv_bfloat16* hi,
                                             __nv_bfloat16* lo, int gidx, int off)
{
    float4 v = *(const float4*)(src + off);
    __nv_bfloat16 h0 = __float2bfloat16_rn(v.x);
    __nv_bfloat16 h1 = __float2bfloat16_rn(v.y);
    __nv_bfloat16 h2 = __float2bfloat16_rn(v.z);
    __nv_bfloat16 h3 = __float2bfloat16_rn(v.w);
    __nv_bfloat16 l0 = __float2bfloat16_rn(v.x - __bfloat162float(h0));
    __nv_bfloat16 l1 = __float2bfloat16_rn(v.y - __bfloat162float(h1));
    __nv_bfloat16 l2 = __float2bfloat16_rn(v.z - __bfloat162float(h2));
    __nv_bfloat16 l3 = __float2bfloat16_rn(v.w - __bfloat162float(h3));
    __nv_bfloat162 hv0; hv0.x = h0; hv0.y = h1;
    __nv_bfloat162 hv1; hv1.x = h2; hv1.y = h3;
    __nv_bfloat162 lv0; lv0.x = l0; lv0.y = l1;
    __nv_bfloat162 lv1; lv1.x = l2; lv1.y = l3;
    *(uint2*)(hi + gidx) = make_uint2(*(uint32_t*)&hv0, *(uint32_t*)&hv1);
    *(uint2*)(lo + gidx) = make_uint2(*(uint32_t*)&lv0, *(uint32_t*)&lv1);
}

__global__ __launch_bounds__(256)
void split_weights_kernel(const float* __restrict__ wq, const float* __restrict__ wk,
                          const float* __restrict__ wv, const float* __restrict__ wo,
                          const float* __restrict__ w1, const float* __restrict__ w2,
                          const float* __restrict__ bq, const float* __restrict__ bk,
                          const float* __restrict__ bv,
                          __nv_bfloat16* __restrict__ hi, __nv_bfloat16* __restrict__ lo,
                          float* __restrict__ biasOut)
{
    const int blk = blockIdx.x;
    if (blk < 3072) {
        int gidx = blk * 1024 + threadIdx.x * 4;
        const float* src;
        int off;
        if (gidx < 262144)        { src = wq; off = gidx; }
        else if (gidx < 524288)   { src = wk; off = gidx - 262144; }
        else if (gidx < 786432)   { src = wv; off = gidx - 524288; }
        else if (gidx < 1048576)  { src = wo; off = gidx - 786432; }
        else if (gidx < 2097152)  { src = w1; off = gidx - 1048576; }
        else                      { src = w2; off = gidx - 2097152; }
        split4_store(src, hi, lo, gidx, off);
    } else {
        int i = (blk - 3072) * 256 + threadIdx.x;   // 0..1535
        if (i < 512)          biasOut[i] = bq[i];
        else if (i < 1024)    biasOut[i] = bk[i - 512];
        else if (i < QKVN)    biasOut[i] = bv[i - 1024];
    }
}

// ---------------------------------------------------------------------------
// fp32 -> bf16 hi/lo split (activations: x)
// ---------------------------------------------------------------------------
__global__ __launch_bounds__(256)
void split_bf16_kernel(const float* __restrict__ in, __nv_bfloat16* __restrict__ hi,
                       __nv_bfloat16* __restrict__ lo, int n)
{
    int i = (blockIdx.x * 256 + threadIdx.x) * 4;
    if (i >= n) return;
    split4_store(in, hi, lo, i, i);
}

// ---------------------------------------------------------------------------
// mma.sync bf16 split-GEMM (validated R16 @ 692.7us; 2 CTAs/SM)
// ---------------------------------------------------------------------------
#define TPAD 40
#define TILE_B (128 * TPAD * 2)
#define STAGE_B (4 * TILE_B)
#define GSMEM (2 * STAGE_B)

__device__ __forceinline__ void gemm_issue(uint32_t sb, int stage, const __nv_bfloat16* const* srcs,
                                           int K, int kt, int tid)
{
    uint32_t stbase = sb + stage * STAGE_B;
    const int k0 = kt * 32;
#pragma unroll
    for (int t = 0; t < 4; t++) {
        const __nv_bfloat16* s = srcs[t] + k0;
#pragma unroll
        for (int i = 0; i < 2; i++) {
            int idx = tid + i * 256;
            int row = idx >> 2, ch = idx & 3;
            cp16(stbase + t * TILE_B + row * (TPAD * 2) + ch * 16,
                 s + (size_t)row * K + ch * 8);
        }
    }
    CP_COMMIT();
}

__global__ __launch_bounds__(256, 2)
void gemm_mma(const __nv_bfloat16* __restrict__ Ahi, const __nv_bfloat16* __restrict__ Alo,
              const __nv_bfloat16* __restrict__ Whi, const __nv_bfloat16* __restrict__ Wlo,
              const float* __restrict__ bias, float* __restrict__ Cf,
              __nv_bfloat16* __restrict__ Chi, __nv_bfloat16* __restrict__ Clo,
              int M, int N, int K, int relu)
{
    extern __shared__ char sm[];
    const uint32_t sb = smem_u32(sm);
    const int tid = threadIdx.x;
    const int wid = tid >> 5;
    const int lane = tid & 31;
    const int bm = blockIdx.y * 128;
    const int bn = blockIdx.x * 128;
    const int wm = (wid & 1) * 64;
    const int wn = (wid >> 1) * 32;

    const __nv_bfloat16* srcs[4];
    srcs[0] = Ahi + (size_t)bm * K;
    srcs[1] = Alo + (size_t)bm * K;
    srcs[2] = Whi + (size_t)bn * K;
    srcs[3] = Wlo + (size_t)bn * K;

    float acc[4][4][4];
#pragma unroll
    for (int i = 0; i < 4; i++)
#pragma unroll
        for (int j = 0; j < 4; j++)
#pragma unroll
            for (int r = 0; r < 4; r++) acc[i][j][r] = 0.f;

    const int KT = K >> 5;
    gemm_issue(sb, 0, srcs, K, 0, tid);
    gemm_issue(sb, 1, srcs, K, 1, tid);

    const int a_lofs = ((((lane >> 3) & 1) << 3) + (lane & 7)) * (TPAD * 2) + ((lane >> 4) << 4);
    const int b_lofs = ((((lane >> 4) & 1) << 3) + (lane & 7)) * (TPAD * 2) + (((lane >> 3) & 1) << 4);

    for (int kt = 0; kt < KT; kt++) {
        if (kt == KT - 1) { CP_WAIT0(); } else { CP_WAIT1(); }
        __syncthreads();
        const uint32_t base = sb + (kt & 1) * STAGE_B;

#pragma unroll
        for (int ks = 0; ks < 2; ks++) {
            uint32_t ah[4][4], al[4][4], bh[4][2], bl[4][2];
            const uint32_t aoff = base + (wm)*(TPAD * 2) + ks * 32 + a_lofs;
            const uint32_t boff = base + 2 * TILE_B + (wn)*(TPAD * 2) + ks * 32 + b_lofs;
#pragma unroll
            for (int i = 0; i < 4; i++) {
                LDSM4(ah[i][0], ah[i][1], ah[i][2], ah[i][3], aoff + i * 16 * (TPAD * 2));
                LDSM4(al[i][0], al[i][1], al[i][2], al[i][3], aoff + TILE_B + i * 16 * (TPAD * 2));
            }
#pragma unroll
            for (int g = 0; g < 2; g++) {
                LDSM4(bh[2 * g][0], bh[2 * g][1], bh[2 * g + 1][0], bh[2 * g + 1][1],
                      boff + g * 16 * (TPAD * 2));
                LDSM4(bl[2 * g][0], bl[2 * g][1], bl[2 * g + 1][0], bl[2 * g + 1][1],
                      boff + TILE_B + g * 16 * (TPAD * 2));
            }
#pragma unroll
            for (int i = 0; i < 4; i++)
#pragma unroll
                for (int j = 0; j < 4; j++) MMA16816(acc[i][j], ah[i], bh[j]);
#pragma unroll
            for (int i = 0; i < 4; i++)
#pragma unroll
                for (int j = 0; j < 4; j++) MMA16816(acc[i][j], al[i], bh[j]);
#pragma unroll
            for (int i = 0; i < 4; i++)
#pragma unroll
                for (int j = 0; j < 4; j++) MMA16816(acc[i][j], ah[i], bl[j]);
        }
        __syncthreads();
        if (kt + 2 < KT) gemm_issue(sb, kt & 1, srcs, K, kt + 2, tid);
    }

    const int rr = lane >> 2;
    const int cc = (lane & 3) * 2;
#pragma unroll
    for (int i = 0; i < 4; i++) {
#pragma unroll
        for (int j = 0; j < 4; j++) {
            int r0 = bm + wm + i * 16 + rr;
            int c = bn + wn + j * 8 + cc;
            float b0 = __ldg(bias + c), b1 = __ldg(bias + c + 1);
            float v00 = acc[i][j][0] + b0, v01 = acc[i][j][1] + b1;
            float v10 = acc[i][j][2] + b0, v11 = acc[i][j][3] + b1;
            if (relu) {
                v00 = fmaxf(v00, 0.f); v01 = fmaxf(v01, 0.f);
                v10 = fmaxf(v10, 0.f); v11 = fmaxf(v11, 0.f);
            }
            size_t o0 = (size_t)r0 * N + c;
            size_t o1 = (size_t)(r0 + 8) * N + c;
            if (Cf) {
                *(float2*)(Cf + o0) = make_float2(v00, v01);
                *(float2*)(Cf + o1) = make_float2(v10, v11);
            }
            if (Chi) {
                __nv_bfloat162 h0 = __floats2bfloat162_rn(v00, v01);
                __nv_bfloat162 h1 = __floats2bfloat162_rn(v10, v11);
                __nv_bfloat162 l0 = __floats2bfloat162_rn(v00 - __bfloat162float(h0.x),
                                                          v01 - __bfloat162float(h0.y));
                __nv_bfloat162 l1 = __floats2bfloat162_rn(v10 - __bfloat162float(h1.x),
                                                          v11 - __bfloat162float(h1.y));
                *(__nv_bfloat162*)(Chi + o0) = h0;
                *(__nv_bfloat162*)(Chi + o1) = h1;
                *(__nv_bfloat162*)(Clo + o0) = l0;
                *(__nv_bfloat162*)(Clo + o1) = l1;
            }
        }
    }
}

// ---------------------------------------------------------------------------
// mma.sync flash attention over COMPACTED keys (validated R12/R16 @ 7.26e-6).
// smem layout (pitch 72 bf16 = 144B/row):
//   sQh 0, sQl 9216, sKh 18432, sKl 27648, sVh 36864, sVl 46080, maskSA 55296
// ---------------------------------------------------------------------------
#define APITCHB 144
#define ATT_SMEM (55296 + 512)

__global__ __launch_bounds__(128, 1)
void attention_mma(const __nv_bfloat16* __restrict__ QKVh, const __nv_bfloat16* __restrict__ QKVl,
                   const float* __restrict__ maskSA, const int* __restrict__ cidx,
                   const int* __restrict__ nb,
                   __nv_bfloat16* __restrict__ Ohi, __nv_bfloat16* __restrict__ Olo)
{
    extern __shared__ char ab[];
    const uint32_t sb = smem_u32(ab);
    const int b = blockIdx.z, h = blockIdx.y, q0 = blockIdx.x * 64;
    const int tid = threadIdx.x, wid = tid >> 5, lane = tid & 31;

    const uint32_t sQh = sb, sQl = sb + 9216;
    const uint32_t sKh = sb + 18432, sKl = sb + 27648;
    const uint32_t sVh = sb + 36864, sVl = sb + 46080;
    const uint32_t sMsk = sb + 55296;

    const int nkeys = nb[b];
    const int ntiles = (nkeys + 63) >> 6;
    const int* cix = cidx + (size_t)b * SS;

    // --- load Q hi/lo tiles (once) ---
    {
        const size_t rb = ((size_t)b * SS + q0) * QKVN + h * DKV;
#pragma unroll
        for (int i = 0; i < 8; i++) {
            int idx = tid + i * 128;             // 0..1023
            int t = idx >> 9;                    // 0 hi, 1 lo
            int row = (idx >> 3) & 63;
            int ch = idx & 7;
            const __nv_bfloat16* src = (t ? QKVl : QKVh) + rb + (size_t)row * QKVN + ch * 8;
            cp16((t ? sQl : sQh) + row * APITCHB + ch * 16, src);
        }
    }
    CP_COMMIT();

    // per-lane row state: row g = lane>>2, row g+8
    float m0 = -1e30f, m1 = -1e30f, l0 = 0.f, l1 = 0.f;
    float o[8][4];
#pragma unroll
    for (int j = 0; j < 8; j++)
#pragma unroll
        for (int r = 0; r < 4; r++) o[j][r] = 0.f;

    // ldmatrix lane offsets
    const uint32_t a_lofs = (uint32_t)((wid * 16 + (((lane >> 3) & 1) << 3) + (lane & 7)) * APITCHB
                                       + ((lane >> 4) << 4));
    const uint32_t b_lofs = (uint32_t)(((((lane >> 4) & 1) << 3) + (lane & 7)) * APITCHB
                                       + (((lane >> 3) & 1) << 4));
    const uint32_t v_lofs = (uint32_t)((lane & 15) * APITCHB + ((lane >> 4) << 4));

    for (int itl = 0; itl < ntiles; itl++) {
        const int j0 = itl * 64;
        // --- load gathered K/V hi/lo tiles + compacted mask (scale,add) ---
#pragma unroll
        for (int i = 0; i < 16; i++) {
            int idx = tid + i * 128;             // 0..2047
            int t = idx >> 9;                    // 0 Kh, 1 Kl, 2 Vh, 3 Vl
            int row = (idx >> 3) & 63;
            int ch = idx & 7;
            const int grow = cix[j0 + row];      // gathered key row (L1-hot)
            const __nv_bfloat16* base = (t == 0 || t == 2) ? QKVh : QKVl;
            size_t goff = ((size_t)b * SS + grow) * QKVN + 512 + ((t >= 2) ? 512 : 0)
                          + h * DKV + ch * 8;
            uint32_t d = (t == 0 ? sKh : t == 1 ? sKl : t == 2 ? sVh : sVl) + row * APITCHB + ch * 16;
            cp16(d, base + goff);
        }
        if (tid < 32) cp16(sMsk + tid * 16, maskSA + ((size_t)b * SS + j0) * 2 + tid * 4);
        CP_COMMIT();
        CP_WAIT0();
        __syncthreads();

        // --- S = Q K^T (3-pass split) ---
        float s[8][4];
#pragma unroll
        for (int j = 0; j < 8; j++)
#pragma unroll
            for (int r = 0; r < 4; r++) s[j][r] = 0.f;

#pragma unroll
        for (int kc = 0; kc < 4; kc++) {
            uint32_t qh[4], ql[4];
            LDSM4(qh[0], qh[1], qh[2], qh[3], sQh + a_lofs + kc * 32);
            LDSM4(ql[0], ql[1], ql[2], ql[3], sQl + a_lofs + kc * 32);
#pragma unroll
            for (int g = 0; g < 4; g++) {
                uint32_t kh0[2], kh1[2], kl0[2], kl1[2];
                LDSM4(kh0[0], kh0[1], kh1[0], kh1[1], sKh + b_lofs + g * 16 * APITCHB + kc * 32);
                LDSM4(kl0[0], kl0[1], kl1[0], kl1[1], sKl + b_lofs + g * 16 * APITCHB + kc * 32);
                MMA16816(s[2 * g],     qh, kh0);
                MMA16816(s[2 * g],     ql, kh0);
                MMA16816(s[2 * g],     qh, kl0);
                MMA16816(s[2 * g + 1], qh, kh1);
                MMA16816(s[2 * g + 1], ql, kh1);
                MMA16816(s[2 * g + 1], qh, kl1);
            }
        }

        // --- scale + mask: s' = s*scale + add (tail slots -> exactly -1e9) ---
#pragma unroll
        for (int j = 0; j < 8; j++) {
            float4 f = *(const float4*)(ab + 55296 + (j * 8 + (lane & 3) * 2) * 8);
            s[j][0] = fmaf(s[j][0], f.x, f.y);
            s[j][1] = fmaf(s[j][1], f.z, f.w);
            s[j][2] = fmaf(s[j][2], f.x, f.y);
            s[j][3] = fmaf(s[j][3], f.z, f.w);
        }

        // --- online softmax ---
        float mx0 = -1e30f, mx1 = -1e30f;
#pragma unroll
        for (int j = 0; j < 8; j++) {
            mx0 = fmaxf(mx0, fmaxf(s[j][0], s[j][1]));
            mx1 = fmaxf(mx1, fmaxf(s[j][2], s[j][3]));
        }
        mx0 = fmaxf(mx0, __shfl_xor_sync(0xffffffffu, mx0, 1));
        mx0 = fmaxf(mx0, __shfl_xor_sync(0xffffffffu, mx0, 2));
        mx1 = fmaxf(mx1, __shfl_xor_sync(0xffffffffu, mx1, 1));
        mx1 = fmaxf(mx1, __shfl_xor_sync(0xffffffffu, mx1, 2));

        float mn0 = fmaxf(m0, mx0), mn1 = fmaxf(m1, mx1);
        float al0 = __expf(m0 - mn0), al1 = __expf(m1 - mn1);
        float sum0 = 0.f, sum1 = 0.f;
#pragma unroll
        for (int j = 0; j < 8; j++) {
            s[j][0] = __expf(s[j][0] - mn0); sum0 += s[j][0];
            s[j][1] = __expf(s[j][1] - mn0); sum0 += s[j][1];
            s[j][2] = __expf(s[j][2] - mn1); sum1 += s[j][2];
            s[j][3] = __expf(s[j][3] - mn1); sum1 += s[j][3];
        }
        sum0 += __shfl_xor_sync(0xffffffffu, sum0, 1);
        sum0 += __shfl_xor_sync(0xffffffffu, sum0, 2);
        sum1 += __shfl_xor_sync(0xffffffffu, sum1, 1);
        sum1 += __shfl_xor_sync(0xffffffffu, sum1, 2);
        l0 = l0 * al0 + sum0; m0 = mn0;
        l1 = l1 * al1 + sum1; m1 = mn1;
#pragma unroll
        for (int j = 0; j < 8; j++) {
            o[j][0] *= al0; o[j][1] *= al0;
            o[j][2] *= al1; o[j][3] *= al1;
        }

        // --- O += P V (3-pass split; P from accumulators) ---
#pragma unroll
        for (int kc = 0; kc < 4; kc++) {
            uint32_t ph[4], pl[4];
            {
                int j = 2 * kc;
                float h00 = s[j][0],   h01 = s[j][1],   h10 = s[j][2],   h11 = s[j][3];
                float g00 = s[j+1][0], g01 = s[j+1][1], g10 = s[j+1][2], g11 = s[j+1][3];
                ph[0] = pack_bf16x2(h00, h01);
                ph[1] = pack_bf16x2(h10, h11);
                ph[2] = pack_bf16x2(g00, g01);
                ph[3] = pack_bf16x2(g10, g11);
                __nv_bfloat162 t0 = *(__nv_bfloat162*)&ph[0];
                __nv_bfloat162 t1 = *(__nv_bfloat162*)&ph[1];
                __nv_bfloat162 t2 = *(__nv_bfloat162*)&ph[2];
                __nv_bfloat162 t3 = *(__nv_bfloat162*)&ph[3];
                pl[0] = pack_bf16x2(h00 - __bfloat162float(t0.x), h01 - __bfloat162float(t0.y));
                pl[1] = pack_bf16x2(h10 - __bfloat162float(t1.x), h11 - __bfloat162float(t1.y));
                pl[2] = pack_bf16x2(g00 - __bfloat162float(t2.x), g01 - __bfloat162float(t2.y));
                pl[3] = pack_bf16x2(g10 - __bfloat162float(t3.x), g11 - __bfloat162float(t3.y));
            }
#pragma unroll
            for (int p = 0; p < 4; p++) {
                uint32_t vh0[2], vh1[2], vl0[2], vl1[2];
                LDSM4T(vh0[0], vh0[1], vh1[0], vh1[1],
                       sVh + v_lofs + kc * 16 * APITCHB + p * 32);
                LDSM4T(vl0[0], vl0[1], vl1[0], vl1[1],
                       sVl + v_lofs + kc * 16 * APITCHB + p * 32);
                MMA16816(o[2 * p],     ph, vh0);
                MMA16816(o[2 * p],     pl, vh0);
                MMA16816(o[2 * p],     ph, vl0);
                MMA16816(o[2 * p + 1], ph, vh1);
                MMA16816(o[2 * p + 1], pl, vh1);
                MMA16816(o[2 * p + 1], ph, vl1);
            }
        }
        __syncthreads();   // done with K/V/mask smem before next iteration's loads
    }

    // --- epilogue: write bf16 hi/lo of O (batch offset included) ---
    const float inv0 = 1.0f / l0, inv1 = 1.0f / l1;
    const size_t rg = (size_t)b * SS + q0 + wid * 16 + (lane >> 2);
    const int cb = h * DKV + (lane & 3) * 2;
#pragma unroll
    for (int j = 0; j < 8; j++) {
        size_t off0 = rg * DD + cb + j * 8;
        size_t off1 = (rg + 8) * DD + cb + j * 8;
        float v00 = o[j][0] * inv0, v01 = o[j][1] * inv0;
        float v10 = o[j][2] * inv1, v11 = o[j][3] * inv1;
        uint32_t h0 = pack_bf16x2(v00, v01);
        uint32_t h1 = pack_bf16x2(v10, v11);
        __nv_bfloat162 t0 = *(__nv_bfloat162*)&h0;
        __nv_bfloat162 t1 = *(__nv_bfloat162*)&h1;
        uint32_t z0 = pack_bf16x2(v00 - __bfloat162float(t0.x), v01 - __bfloat162float(t0.y));
        uint32_t z1 = pack_bf16x2(v10 - __bfloat162float(t1.x), v11 - __bfloat162float(t1.y));
        *(uint32_t*)(Ohi + off0) = h0;
        *(uint32_t*)(Ohi + off1) = h1;
        *(uint32_t*)(Olo + off0) = z0;
        *(uint32_t*)(Olo + off1) = z1;
    }
}

// ---------------------------------------------------------------------------
// Residual + LayerNorm (unbiased var, scalar gamma/beta), optional bf16 split
// ---------------------------------------------------------------------------
__global__ __launch_bounds__(128)
void ln_add_kernel(const float* __restrict__ X, const float* __restrict__ Z,
                   const float* __restrict__ g, const float* __restrict__ beta,
                   float* __restrict__ Out,
                   __nv_bfloat16* __restrict__ Ohi, __nv_bfloat16* __restrict__ Olo)
{
    __shared__ float red[4];
    const int row = blockIdx.x;
    const int t = threadIdx.x;
    const float4 zv = ((const float4*)(Z + (size_t)row * DD))[t];

    float s = zv.x + zv.y + zv.z + zv.w;
#pragma unroll
    for (int off = 16; off > 0; off >>= 1) s += __shfl_down_sync(0xffffffffu, s, off);
    if ((t & 31) == 0) red[t >> 5] = s;
    __syncthreads();
    float mean = (red[0] + red[1] + red[2] + red[3]) * (1.0f / DD);
    __syncthreads();

    float d0 = zv.x - mean, d1 = zv.y - mean, d2 = zv.z - mean, d3 = zv.w - mean;
    float ss = d0 * d0 + d1 * d1 + d2 * d2 + d3 * d3;
#pragma unroll
    for (int off = 16; off > 0; off >>= 1) ss += __shfl_down_sync(0xffffffffu, ss, off);
    if ((t & 31) == 0) red[t >> 5] = ss;
    __syncthreads();
    float var = (red[0] + red[1] + red[2] + red[3]) * (1.0f / (DD - 1));

    float inv = rsqrtf(var + 1e-6f);
    float gg = *g, bb = *beta;

    const float4 xv = ((const float4*)(X + (size_t)row * DD))[t];
    float4 o;
    o.x = xv.x + gg * d0 * inv + bb;
    o.y = xv.y + gg * d1 * inv + bb;
    o.z = xv.z + gg * d2 * inv + bb;
    o.w = xv.w + gg * d3 * inv + bb;
    ((float4*)(Out + (size_t)row * DD))[t] = o;

    if (Ohi) {
        size_t off = (size_t)row * DD + t * 4;
        __nv_bfloat162 h0 = __floats2bfloat162_rn(o.x, o.y);
        __nv_bfloat162 h1 = __floats2bfloat162_rn(o.z, o.w);
        __nv_bfloat162 l0 = __floats2bfloat162_rn(o.x - __bfloat162float(h0.x),
                                                  o.y - __bfloat162float(h0.y));
        __nv_bfloat162 l1 = __floats2bfloat162_rn(o.z - __bfloat162float(h1.x),
                                                  o.w - __bfloat162float(h1.y));
        *(__nv_bfloat162*)(Ohi + off)     = h0;
        *(__nv_bfloat162*)(Ohi + off + 2) = h1;
        *(__nv_bfloat162*)(Olo + off)     = l0;
        *(__nv_bfloat162*)(Olo + off + 2) = l1;
    }
}

// ---------------------------------------------------------------------------
// Launch
// ---------------------------------------------------------------------------
extern "C" void kernel_launch(void* const* d_in, const int* in_sizes, int n_in,
                              void* d_out, int out_size)
{
    const float* x    = (const float*)d_in[0];
    const void*  mraw = (const void*)d_in[1];
    const float* wq   = (const float*)d_in[2];
    const float* bq   = (const float*)d_in[3];
    const float* wk   = (const float*)d_in[4];
    const float* bk   = (const float*)d_in[5];
    const float* wv   = (const float*)d_in[6];
    const float* bv   = (const float*)d_in[7];
    const float* wo   = (const float*)d_in[8];
    const float* bo   = (const float*)d_in[9];
    const float* w1   = (const float*)d_in[10];
    const float* b1   = (const float*)d_in[11];
    const float* w2   = (const float*)d_in[12];
    const float* b2   = (const float*)d_in[13];
    const float* g1   = (const float*)d_in[14];
    const float* be1  = (const float*)d_in[15];
    const float* g2   = (const float*)d_in[16];
    const float* be2  = (const float*)d_in[17];
    float* out = (float*)d_out;

    float *pO, *pY, *pBias, *pMSA;
    __nv_bfloat16 *pQKVh, *pQKVl, *pAhi, *pAlo, *pFhi, *pFlo, *pWhi, *pWlo;
    int *pCidx, *pNb;
    cudaGetSymbolAddress((void**)&pO, g_O);
    cudaGetSymbolAddress((void**)&pY, g_Y);
    cudaGetSymbolAddress((void**)&pQKVh, g_QKVh);
    cudaGetSymbolAddress((void**)&pQKVl, g_QKVl);
    cudaGetSymbolAddress((void**)&pAhi, g_Ahi);
    cudaGetSymbolAddress((void**)&pAlo, g_Alo);
    cudaGetSymbolAddress((void**)&pFhi, g_Fhi);
    cudaGetSymbolAddress((void**)&pFlo, g_Flo);
    cudaGetSymbolAddress((void**)&pWhi, g_Whi);
    cudaGetSymbolAddress((void**)&pWlo, g_Wlo);
    cudaGetSymbolAddress((void**)&pBias, g_biasQKV);
    cudaGetSymbolAddress((void**)&pMSA, g_maskSA);
    cudaGetSymbolAddress((void**)&pCidx, g_cidx);
    cudaGetSymbolAddress((void**)&pNb, g_nb);

    cudaFuncSetAttribute(gemm_mma, cudaFuncAttributeMaxDynamicSharedMemorySize, GSMEM);
    cudaFuncSetAttribute(attention_mma, cudaFuncAttributeMaxDynamicSharedMemorySize, ATT_SMEM);

    // prep: 3 launches total (was 9)
    compact_mask_kernel<<<BB, 512>>>(mraw, pCidx, pMSA, pNb);
    split_weights_kernel<<<3078, 256>>>(wq, wk, wv, wo, w1, w2, bq, bk, bv,
                                        pWhi, pWlo, pBias);
    split_bf16_kernel<<<(MM * DD) / 1024, 256>>>(x, pAhi, pAlo, MM * DD);

    // fused QKV projection -> bf16 hi/lo only
    dim3 gQKV(QKVN / 128, MM / 128);
    gemm_mma<<<gQKV, 256, GSMEM>>>(pAhi, pAlo, pWhi + WOFF_QKV, pWlo + WOFF_QKV,
                                   pBias, ((float*)0), pQKVh, pQKVl,
                                   MM, QKVN, DD, 0);

    // attention over compacted keys (tensor-core, R7 tiling)
    dim3 gAtt(SS / 64, HH, BB);
    attention_mma<<<gAtt, 128, ATT_SMEM>>>(pQKVh, pQKVl, pMSA, pCidx, pNb, pAhi, pAlo);

    // WO projection -> fp32 pO
    dim3 gProj(DD / 128, MM / 128);
    gemm_mma<<<gProj, 256, GSMEM>>>(pAhi, pAlo, pWhi + WOFF_O, pWlo + WOFF_O,
                                    bo, pO, ((__nv_bfloat16*)0), ((__nv_bfloat16*)0),
                                    MM, DD, DD, 0);

    // residual 1 + LN -> Y (fp32) + split into pAhi/pAlo
    ln_add_kernel<<<MM, 128>>>(x, pO, g1, be1, pY, pAhi, pAlo);

    // FFN1: relu, bf16 split out only
    dim3 gFF1(DFF / 128, MM / 128);
    gemm_mma<<<gFF1, 256, GSMEM>>>(pAhi, pAlo, pWhi + WOFF_1, pWlo + WOFF_1,
                                   b1, ((float*)0), pFhi, pFlo,
                                   MM, DFF, DD, 1);

    // FFN2 -> fp32 pO
    gemm_mma<<<gProj, 256, GSMEM>>>(pFhi, pFlo, pWhi + WOFF_2, pWlo + WOFF_2,
                                    b2, pO, ((__nv_bfloat16*)0), ((__nv_bfloat16*)0),
                                    MM, DD, DFF, 0);

    // residual 2 + LN -> out
    ln_add_kernel<<<MM, 128>>>(pY, pO, g2, be2, out, ((__nv_bfloat16*)0), ((__nv_bfloat16*)0));
}